// round 4
// baseline (speedup 1.0000x reference)
#include <cuda_runtime.h>
#include <cuda_bf16.h>
#include <cstdint>
#include <math.h>

#define NTOK   49
#define CDIM   256
#define HEADS  8
#define HDIM   32
#define BWIN   4096
#define TOKS   (BWIN*NTOK)          // 200704 = 1568 * 128
#define KDA    512                  // A storage: hi | lo
#define KDB    768                  // B storage: hi | hi | lo
#define SCALE  0.17677669529663688f

// ---------------- scratch (device globals; no allocs) ----------------
__device__ __nv_bfloat16 g_A1[(size_t)TOKS*KDA];  // x split   [t][512]
__device__ __nv_bfloat16 g_A2[(size_t)TOKS*KDA];  // attn-out split
__device__ float         g_KV[(size_t)TOKS*512];  // k(0:256) v(256:512) fp32
__device__ __nv_bfloat16 g_B1[512*KDB];           // qkv_w split  [n][768]
__device__ __nv_bfloat16 g_B2[256*KDB];           // proj_w split
__device__ float         g_biasT[HEADS*NTOK*NTOK];// [h][key][query]

// ---------------- helpers ----------------
__device__ __forceinline__ uint32_t smem_u32(const void* p){
    uint32_t a;
    asm("{ .reg .u64 t; cvta.to.shared.u64 t, %1; cvt.u32.u64 %0, t; }" : "=r"(a) : "l"(p));
    return a;
}
__device__ __forceinline__ void cp_async16(uint32_t dst, const void* src){
    asm volatile("cp.async.cg.shared.global [%0], [%1], 16;" :: "r"(dst), "l"(src));
}
#define CP_COMMIT() asm volatile("cp.async.commit_group;")
#define CP_WAIT1()  asm volatile("cp.async.wait_group 1;")
#define CP_WAIT0()  asm volatile("cp.async.wait_group 0;")

__device__ __forceinline__ void ldmx4(uint32_t* r, uint32_t addr){
    asm volatile("ldmatrix.sync.aligned.m8n8.x4.shared.b16 {%0,%1,%2,%3}, [%4];"
        : "=r"(r[0]), "=r"(r[1]), "=r"(r[2]), "=r"(r[3]) : "r"(addr));
}
__device__ __forceinline__ void mma16816(float* c, const uint32_t* a, const uint32_t* b){
    asm volatile("mma.sync.aligned.m16n8k16.row.col.f32.bf16.bf16.f32 "
        "{%0,%1,%2,%3}, {%4,%5,%6,%7}, {%8,%9}, {%0,%1,%2,%3};"
        : "+f"(c[0]), "+f"(c[1]), "+f"(c[2]), "+f"(c[3])
        : "r"(a[0]), "r"(a[1]), "r"(a[2]), "r"(a[3]), "r"(b[0]), "r"(b[1]));
}

// packed f32x2 helpers (base sm_100, PTX 8.6)
typedef unsigned long long u64t;
__device__ __forceinline__ u64t pk2(float lo, float hi){
    u64t r; asm("mov.b64 %0, {%1, %2};" : "=l"(r) : "f"(lo), "f"(hi)); return r;
}
__device__ __forceinline__ void upk2(float& lo, float& hi, u64t v){
    asm("mov.b64 {%0, %1}, %2;" : "=f"(lo), "=f"(hi) : "l"(v));
}
__device__ __forceinline__ void ffma2(u64t& c, u64t a, u64t b){
    asm("fma.rn.f32x2 %0, %1, %2, %3;" : "=l"(c) : "l"(a), "l"(b), "l"(c));
}

// ---------------- prep: weights -> split bf16, bias transpose ----------------
__global__ void prep_w(const float* __restrict__ qkv_w,
                       const float* __restrict__ proj_w,
                       const float* __restrict__ rbt)
{
    int idx = blockIdx.x * 256 + threadIdx.x;   // 1536*256 = 393216 = 512*768
    if (idx < 512*768) {
        int j = idx / 768, c = idx % 768;
        int cc = c & 255, sect = c >> 8;
        float wv = qkv_w[j*256 + cc];
        __nv_bfloat16 hi = __float2bfloat16(wv);
        g_B1[idx] = (sect < 2) ? hi : __float2bfloat16(wv - __bfloat162float(hi));
    }
    if (idx < 256*768) {
        int j = idx / 768, c = idx % 768;
        int cc = c & 255, sect = c >> 8;
        float wv = proj_w[j*256 + cc];
        __nv_bfloat16 hi = __float2bfloat16(wv);
        g_B2[idx] = (sect < 2) ? hi : __float2bfloat16(wv - __bfloat162float(hi));
    }
    if (idx < HEADS*NTOK*NTOK) {
        int h = idx / (NTOK*NTOK);
        int r = idx % (NTOK*NTOK);
        int i = r / NTOK, j = r % NTOK;     // i=query, j=key
        int ai = i / 7, aj = i % 7, bi = j / 7, bj = j % 7;
        int t = (ai - bi + 6) * 13 + (aj - bj + 6);
        g_biasT[(h*NTOK + j)*NTOK + i] = rbt[t*HEADS + h];
    }
}

// ---------------- convert x -> A1 (hi|lo) ----------------
__global__ void conv_x(const float* __restrict__ x)
{
    size_t t = blockIdx.x;
    int c = threadIdx.x;
    float v = x[t*CDIM + c];
    __nv_bfloat16 hi = __float2bfloat16(v);
    __nv_bfloat16 lo = __float2bfloat16(v - __bfloat162float(hi));
    size_t rb = t * KDA;
    g_A1[rb + c]       = hi;
    g_A1[rb + 256 + c] = lo;
}

// ---------------- mma.sync bf16 GEMM: C[128,128] per CTA, K'=768 ----------------
#define GSTAGE 16384     // bytes per (A or B) stage: 128*64*2
#define GSMEM  (4*GSTAGE)

template<int NOUT>
__global__ void __launch_bounds__(256)
gemm_k(const float* __restrict__ bias, float* __restrict__ extC)
{
    extern __shared__ char sm[];
    const __nv_bfloat16* Ag = (NOUT == 512) ? g_A1 : g_A2;
    const __nv_bfloat16* Bg = (NOUT == 512) ? g_B1 : g_B2;
    float* C = (NOUT == 512) ? g_KV : extC;

    const int tid = threadIdx.x;
    const int m0 = blockIdx.x * 128;
    const int n0 = blockIdx.y * 128;
    const uint32_t sb = smem_u32(sm);

    // async loader: A chunk i<8 reads cols i*64 of [hi|lo]; i>=8 re-reads hi
    auto load_stage = [&](int i, int s){
        int aoff = (i < 8) ? i*64 : (i-8)*64;
        const char* Abase = (const char*)Ag + ((size_t)m0*KDA + (size_t)aoff)*2;
        const char* Bbase = (const char*)Bg + ((size_t)n0*KDB + (size_t)i*64)*2;
        uint32_t sa  = sb + s*GSTAGE;
        uint32_t sbB = sb + 2*GSTAGE + s*GSTAGE;
        #pragma unroll
        for (int u = 0; u < 4; u++) {
            int idx = tid + u*256;          // 0..1023
            int r = idx >> 3, c16 = idx & 7;
            uint32_t dst = (uint32_t)(r*128 + ((c16 ^ (r & 7))*16));
            cp_async16(sa  + dst, Abase + (size_t)r*(KDA*2) + c16*16);
            cp_async16(sbB + dst, Bbase + (size_t)r*(KDB*2) + c16*16);
        }
        CP_COMMIT();
    };

    const int w = tid >> 5, lane = tid & 31;
    const int wm = w >> 1, wn = w & 1;       // 4 x 2 warp grid
    const int aRow = wm*32 + (lane & 15);
    const int aC16 = (lane >> 4);
    const int bRow = wn*64 + (lane & 7) + ((lane >> 4) << 3);
    const int bC16 = (lane >> 3) & 1;

    float acc[2][8][4];
    #pragma unroll
    for (int mt = 0; mt < 2; mt++)
        #pragma unroll
        for (int nt = 0; nt < 8; nt++)
            #pragma unroll
            for (int q = 0; q < 4; q++) acc[mt][nt][q] = 0.f;

    load_stage(0, 0);
    for (int i = 0; i < 12; i++) {
        const int s = i & 1;
        if (i < 11) { load_stage(i+1, s^1); CP_WAIT1(); }
        else        { CP_WAIT0(); }
        __syncthreads();
        const uint32_t sa  = sb + s*GSTAGE;
        const uint32_t sbB = sb + 2*GSTAGE + s*GSTAGE;
        #pragma unroll
        for (int kk = 0; kk < 4; kk++) {
            uint32_t af[2][4];
            #pragma unroll
            for (int mt = 0; mt < 2; mt++) {
                int r = aRow + mt*16, c = kk*2 + aC16;
                ldmx4(af[mt], sa + r*128 + ((c ^ (r & 7))*16));
            }
            #pragma unroll
            for (int np = 0; np < 4; np++) {
                uint32_t bf[4];
                int r = bRow + np*16, c = kk*2 + bC16;
                ldmx4(bf, sbB + r*128 + ((c ^ (r & 7))*16));
                #pragma unroll
                for (int mt = 0; mt < 2; mt++) {
                    mma16816(acc[mt][np*2+0], af[mt], bf+0);
                    mma16816(acc[mt][np*2+1], af[mt], bf+2);
                }
            }
        }
        __syncthreads();
    }

    #pragma unroll
    for (int nt = 0; nt < 8; nt++) {
        int col = n0 + wn*64 + nt*8 + (lane & 3)*2;
        float bx = __ldg(bias + col), by = __ldg(bias + col + 1);
        #pragma unroll
        for (int mt = 0; mt < 2; mt++) {
            int row = m0 + wm*32 + mt*16 + (lane >> 2);
            float2 v0 = make_float2(acc[mt][nt][0] + bx, acc[mt][nt][1] + by);
            float2 v1 = make_float2(acc[mt][nt][2] + bx, acc[mt][nt][3] + by);
            *(float2*)(C + (size_t)row*NOUT + col)       = v0;
            *(float2*)(C + (size_t)(row+8)*NOUT + col)   = v1;
        }
    }
}

// ---------------- attention: f32x2 packed, kT transpose, direct split out ----
// smem: kT [8 heads][32 d][52 kj-padded] floats + v [49][256] floats
#define KT_W   52
#define KT_W64 26
#define SM_KT_F (HEADS*HDIM*KT_W)          // 13312
#define SM_V_F  (NTOK*256)                 // 12544
#define ATTN_SMEM ((SM_KT_F + SM_V_F)*4)   // 103424 B

__global__ void __launch_bounds__(512, 1)
attn_k(const float* __restrict__ qg)
{
    extern __shared__ float smf[];
    float* s_kT = smf;                 // [(h*32+d)*52 + kj]
    float* s_v  = smf + SM_KT_F;       // [kj][256]

    const int tid = threadIdx.x;
    const int b   = blockIdx.x;

    // stage: k -> transposed, v -> row-major
    {
        const float4* src = (const float4*)(g_KV + (size_t)b * NTOK * 512);
        for (int u = tid; u < NTOK*128; u += 512) {
            int n = u >> 7, c4 = u & 127;
            float4 v = __ldg(src + n*128 + c4);
            int c = c4 * 4;
            if (c < 256) {
                int base = c;   // h = c>>5, d = c&31 ; rows consecutive in d
                s_kT[(base+0)*KT_W + n] = v.x;
                s_kT[(base+1)*KT_W + n] = v.y;
                s_kT[(base+2)*KT_W + n] = v.z;
                s_kT[(base+3)*KT_W + n] = v.w;
            } else {
                *(float4*)(s_v + n*256 + (c - 256)) = v;
            }
        }
    }
    __syncthreads();

    const int w = tid >> 5, lane = tid & 31;
    const int h = w & 7, p = w >> 3;
    const int qi = p*32 + lane;
    const bool act = qi < NTOK;
    const int qis = act ? qi : 0;

    // q (scaled; 0 for inactive lanes)
    float qv[32];
    {
        const float4* qr = (const float4*)(qg + (((size_t)(b >> 6)*HEADS + h)*NTOK + qis)*HDIM);
        float m = act ? SCALE : 0.f;
        #pragma unroll
        for (int d4 = 0; d4 < 8; d4++) {
            float4 t = __ldg(qr + d4);
            qv[d4*4+0] = t.x*m; qv[d4*4+1] = t.y*m;
            qv[d4*4+2] = t.z*m; qv[d4*4+3] = t.w*m;
        }
    }

    // QK: packed over key pairs; 25 packed accumulators
    u64t s2[25];
    #pragma unroll
    for (int j = 0; j < 25; j++) s2[j] = 0ull;
    {
        const u64t* kT64 = (const u64t*)s_kT;
        const u64t* row = kT64 + (size_t)h*HDIM*KT_W64;
        #pragma unroll 4
        for (int d = 0; d < 32; d++) {
            u64t qd2 = pk2(qv[d], qv[d]);
            const u64t* kr = row + d*KT_W64;
            #pragma unroll
            for (int j = 0; j < 25; j++) ffma2(s2[j], qd2, kr[j]);
        }
    }

    // unpack + bias + softmax
    float s[NTOK];
    const float* bh = g_biasT + h*NTOK*NTOK + qis;
    float mx = -1e30f;
    #pragma unroll
    for (int j = 0; j < 24; j++) {
        float a, c;
        upk2(a, c, s2[j]);
        a += __ldg(bh + (2*j)*NTOK);
        c += __ldg(bh + (2*j+1)*NTOK);
        s[2*j] = a; s[2*j+1] = c;
        mx = fmaxf(mx, fmaxf(a, c));
    }
    {
        float a, c;
        upk2(a, c, s2[24]);
        a += __ldg(bh + 48*NTOK);
        s[48] = a;
        mx = fmaxf(mx, a);
    }
    float den = 0.f;
    #pragma unroll
    for (int kj = 0; kj < NTOK; kj++) { s[kj] = __expf(s[kj] - mx); den += s[kj]; }
    float rinv = 1.f / den;

    // PV: packed over dim pairs, 16 independent accumulators
    u64t o2[16];
    #pragma unroll
    for (int t = 0; t < 16; t++) o2[t] = 0ull;
    #pragma unroll 4
    for (int kj = 0; kj < NTOK; kj++) {
        u64t p2 = pk2(s[kj], s[kj]);
        const ulonglong2* vr = (const ulonglong2*)(s_v + kj*256 + h*HDIM);
        #pragma unroll
        for (int t = 0; t < 8; t++) {
            ulonglong2 vv = vr[t];
            ffma2(o2[2*t+0], p2, vv.x);
            ffma2(o2[2*t+1], p2, vv.y);
        }
    }

    // output: normalize, split hi/lo bf16, store to g_A2 [t][512]
    if (act) {
        uint32_t hiw[16], low[16];
        #pragma unroll
        for (int t = 0; t < 16; t++) {
            float a, c;
            upk2(a, c, o2[t]);
            a *= rinv; c *= rinv;
            __nv_bfloat16 ha = __float2bfloat16(a);
            __nv_bfloat16 hc = __float2bfloat16(c);
            __nv_bfloat16 la = __float2bfloat16(a - __bfloat162float(ha));
            __nv_bfloat16 lc = __float2bfloat16(c - __bfloat162float(hc));
            hiw[t] = (uint32_t)__bfloat16_as_ushort(ha) | ((uint32_t)__bfloat16_as_ushort(hc) << 16);
            low[t] = (uint32_t)__bfloat16_as_ushort(la) | ((uint32_t)__bfloat16_as_ushort(lc) << 16);
        }
        __nv_bfloat16* dst = g_A2 + ((size_t)b*NTOK + qi)*KDA + h*HDIM;
        #pragma unroll
        for (int t4 = 0; t4 < 4; t4++) {
            *(uint4*)(dst + t4*8)       = make_uint4(hiw[t4*4], hiw[t4*4+1], hiw[t4*4+2], hiw[t4*4+3]);
            *(uint4*)(dst + 256 + t4*8) = make_uint4(low[t4*4], low[t4*4+1], low[t4*4+2], low[t4*4+3]);
        }
    }
}

// ---------------- launch ----------------
extern "C" void kernel_launch(void* const* d_in, const int* in_sizes, int n_in,
                              void* d_out, int out_size)
{
    const float* x      = (const float*)d_in[0];
    const float* qg     = (const float*)d_in[1];
    const float* qkv_w  = (const float*)d_in[2];
    const float* qkv_b  = (const float*)d_in[3];
    const float* proj_w = (const float*)d_in[4];
    const float* proj_b = (const float*)d_in[5];
    const float* rbt    = (const float*)d_in[6];
    float* out = (float*)d_out;
    (void)in_sizes; (void)n_in; (void)out_size;

    cudaFuncSetAttribute(gemm_k<512>, cudaFuncAttributeMaxDynamicSharedMemorySize, GSMEM);
    cudaFuncSetAttribute(gemm_k<256>, cudaFuncAttributeMaxDynamicSharedMemorySize, GSMEM);
    cudaFuncSetAttribute(attn_k,      cudaFuncAttributeMaxDynamicSharedMemorySize, ATTN_SMEM);

    prep_w<<<1536, 256>>>(qkv_w, proj_w, rbt);
    conv_x<<<TOKS, 256>>>(x);
    {
        dim3 g1(TOKS/128, 4);
        gemm_k<512><<<g1, 256, GSMEM>>>(qkv_b, nullptr);
    }
    attn_k<<<BWIN, 512, ATTN_SMEM>>>(qg);
    {
        dim3 g2(TOKS/128, 2);
        gemm_k<256><<<g2, 256, GSMEM>>>(proj_b, out);
    }
}

// round 5
// speedup vs baseline: 1.2335x; 1.2335x over previous
#include <cuda_runtime.h>
#include <cuda_bf16.h>
#include <cstdint>
#include <math.h>

#define NTOK   49
#define CDIM   256
#define HEADS  8
#define HDIM   32
#define BWIN   4096
#define TOKS   (BWIN*NTOK)          // 200704 = 1568 * 128
#define KDA    512                  // A storage: hi | lo
#define KDB    768                  // B storage: hi | hi | lo
#define SCALE  0.17677669529663688f

// ---------------- scratch (device globals; no allocs) ----------------
__device__ __nv_bfloat16 g_A1[(size_t)TOKS*KDA];  // x split   [t][512]
__device__ __nv_bfloat16 g_A2[(size_t)TOKS*KDA];  // attn-out split
__device__ __nv_bfloat16 g_B1[512*KDB];           // qkv_w split  [n][768]
__device__ __nv_bfloat16 g_B2[256*KDB];           // proj_w split
// K tiles: [win][head] 64 tok-rows x 128B (32 bf16 hi | 32 lo), swizzled. pads stay 0.
__device__ unsigned char g_Ks[(size_t)BWIN*HEADS*8192];
// V tiles: [win][head] { hi: 32 dim-rows x 128B (64 tok bf16) ; lo same } = 8KB. pads stay 0.
__device__ unsigned char g_Vt[(size_t)BWIN*HEADS*8192];
// Q fragments: [img][head][mtile 4][kind 4][lane 32] uint4 (a0..a3 bf16x2)
__device__ uint4  g_Qf[64*HEADS*4*4*32];
// bias in C-fragment layout, mask folded: [head][mtile 4][ntile 7][lane 32] float4
__device__ float4 g_biasF[HEADS*4*7*32];

// ---------------- helpers ----------------
__device__ __forceinline__ uint32_t smem_u32(const void* p){
    uint32_t a;
    asm("{ .reg .u64 t; cvta.to.shared.u64 t, %1; cvt.u32.u64 %0, t; }" : "=r"(a) : "l"(p));
    return a;
}
__device__ __forceinline__ void cp_async16(uint32_t dst, const void* src){
    asm volatile("cp.async.cg.shared.global [%0], [%1], 16;" :: "r"(dst), "l"(src));
}
#define CP_COMMIT() asm volatile("cp.async.commit_group;")
#define CP_WAIT1()  asm volatile("cp.async.wait_group 1;")
#define CP_WAIT0()  asm volatile("cp.async.wait_group 0;")

__device__ __forceinline__ void ldmx4(uint32_t* r, uint32_t addr){
    asm volatile("ldmatrix.sync.aligned.m8n8.x4.shared.b16 {%0,%1,%2,%3}, [%4];"
        : "=r"(r[0]), "=r"(r[1]), "=r"(r[2]), "=r"(r[3]) : "r"(addr));
}
__device__ __forceinline__ void mma16816(float* c, const uint32_t* a, const uint32_t* b){
    asm volatile("mma.sync.aligned.m16n8k16.row.col.f32.bf16.bf16.f32 "
        "{%0,%1,%2,%3}, {%4,%5,%6,%7}, {%8,%9}, {%0,%1,%2,%3};"
        : "+f"(c[0]), "+f"(c[1]), "+f"(c[2]), "+f"(c[3])
        : "r"(a[0]), "r"(a[1]), "r"(a[2]), "r"(a[3]), "r"(b[0]), "r"(b[1]));
}
__device__ __forceinline__ uint32_t pkbf(__nv_bfloat16 a, __nv_bfloat16 b){
    return (uint32_t)__bfloat16_as_ushort(a) | ((uint32_t)__bfloat16_as_ushort(b) << 16);
}
__device__ __forceinline__ int rpi(int r, int c){
    int ai = r/7, aj = r%7, bi = c/7, bj = c%7;
    return (ai - bi + 6)*13 + (aj - bj + 6);
}

// ---------------- prep: weights split, bias fragments ----------------
__global__ void prep_w(const float* __restrict__ qkv_w,
                       const float* __restrict__ proj_w,
                       const float* __restrict__ rbt)
{
    int idx = blockIdx.x * 256 + threadIdx.x;   // 1536*256 = 393216
    if (idx < 512*768) {
        int j = idx / 768, c = idx % 768;
        int cc = c & 255, sect = c >> 8;
        float wv = qkv_w[j*256 + cc];
        __nv_bfloat16 hi = __float2bfloat16(wv);
        g_B1[idx] = (sect < 2) ? hi : __float2bfloat16(wv - __bfloat162float(hi));
    }
    if (idx < 256*768) {
        int j = idx / 768, c = idx % 768;
        int cc = c & 255, sect = c >> 8;
        float wv = proj_w[j*256 + cc];
        __nv_bfloat16 hi = __float2bfloat16(wv);
        g_B2[idx] = (sect < 2) ? hi : __float2bfloat16(wv - __bfloat162float(hi));
    }
    if (idx < HEADS*4*7*32) {
        int lane = idx & 31;
        int nt = (idx >> 5) % 7;
        int mt = (idx >> 5) / 7 % 4;
        int h  = idx / (32*7*4);
        int r0 = mt*16 + (lane>>2), r1 = r0 + 8;
        int c0 = nt*8 + 2*(lane&3), c1 = c0 + 1;
        float4 v;
        v.x = (r0 < 49 && c0 < 49) ? rbt[rpi(r0,c0)*HEADS + h] : -1e30f;
        v.y = (r0 < 49 && c1 < 49) ? rbt[rpi(r0,c1)*HEADS + h] : -1e30f;
        v.z = (r1 < 49 && c0 < 49) ? rbt[rpi(r1,c0)*HEADS + h] : -1e30f;
        v.w = (r1 < 49 && c1 < 49) ? rbt[rpi(r1,c1)*HEADS + h] : -1e30f;
        g_biasF[idx] = v;
    }
}

// ---------------- prep: Q -> A-fragments (scaled, hi/lo split) ----------------
__global__ void prep_q(const float* __restrict__ qg)
{
    int idx = blockIdx.x * 256 + threadIdx.x;   // 1024*256 = 262144
    int lane = idx & 31;
    int kind = (idx >> 5) & 3;
    int mt   = (idx >> 7) & 3;
    int h    = (idx >> 9) & 7;
    int img  = idx >> 12;
    int r = mt*16 + (lane>>2);
    int c2 = 2*(lane&3);
    int db = (kind & 1) * 16;     // dim block
    bool lo = kind >= 2;

    auto qget = [&](int rr, int d) -> __nv_bfloat16 {
        if (rr >= 49) return __float2bfloat16(0.f);
        float v = qg[(((size_t)img*HEADS + h)*NTOK + rr)*HDIM + d] * SCALE;
        __nv_bfloat16 hv = __float2bfloat16(v);
        if (!lo) return hv;
        return __float2bfloat16(v - __bfloat162float(hv));
    };
    uint4 o;
    o.x = pkbf(qget(r,   db+c2),   qget(r,   db+c2+1));
    o.y = pkbf(qget(r+8, db+c2),   qget(r+8, db+c2+1));
    o.z = pkbf(qget(r,   db+c2+8), qget(r,   db+c2+9));
    o.w = pkbf(qget(r+8, db+c2+8), qget(r+8, db+c2+9));
    g_Qf[idx] = o;
}

// ---------------- convert x -> A1 (hi|lo) ----------------
__global__ void conv_x(const float* __restrict__ x)
{
    size_t t = blockIdx.x;
    int c = threadIdx.x;
    float v = x[t*CDIM + c];
    __nv_bfloat16 hi = __float2bfloat16(v);
    __nv_bfloat16 lo = __float2bfloat16(v - __bfloat162float(hi));
    size_t rb = t * KDA;
    g_A1[rb + c]       = hi;
    g_A1[rb + 256 + c] = lo;
}

// ---------------- mma.sync bf16 GEMM: C[128,128] per CTA, K'=768 ----------------
#define GSTAGE 16384
#define GSMEM  (4*GSTAGE)

template<int NOUT>
__global__ void __launch_bounds__(256)
gemm_k(const float* __restrict__ bias, float* __restrict__ extC)
{
    extern __shared__ char sm[];
    const __nv_bfloat16* Ag = (NOUT == 512) ? g_A1 : g_A2;
    const __nv_bfloat16* Bg = (NOUT == 512) ? g_B1 : g_B2;

    const int tid = threadIdx.x;
    const int m0 = blockIdx.x * 128;
    const int n0 = blockIdx.y * 128;
    const uint32_t sb = smem_u32(sm);

    auto load_stage = [&](int i, int s){
        int aoff = (i < 8) ? i*64 : (i-8)*64;
        const char* Abase = (const char*)Ag + ((size_t)m0*KDA + (size_t)aoff)*2;
        const char* Bbase = (const char*)Bg + ((size_t)n0*KDB + (size_t)i*64)*2;
        uint32_t sa  = sb + s*GSTAGE;
        uint32_t sbB = sb + 2*GSTAGE + s*GSTAGE;
        #pragma unroll
        for (int u = 0; u < 4; u++) {
            int idx = tid + u*256;
            int r = idx >> 3, c16 = idx & 7;
            uint32_t dst = (uint32_t)(r*128 + ((c16 ^ (r & 7))*16));
            cp_async16(sa  + dst, Abase + (size_t)r*(KDA*2) + c16*16);
            cp_async16(sbB + dst, Bbase + (size_t)r*(KDB*2) + c16*16);
        }
        CP_COMMIT();
    };

    const int w = tid >> 5, lane = tid & 31;
    const int wm = w >> 1, wn = w & 1;
    const int aRow = wm*32 + (lane & 15);
    const int aC16 = (lane >> 4);
    const int bRow = wn*64 + (lane & 7) + ((lane >> 4) << 3);
    const int bC16 = (lane >> 3) & 1;
    const int lc2 = 2*(lane & 3);

    float acc[2][8][4];
    #pragma unroll
    for (int mt = 0; mt < 2; mt++)
        #pragma unroll
        for (int nt = 0; nt < 8; nt++)
            #pragma unroll
            for (int q = 0; q < 4; q++) acc[mt][nt][q] = 0.f;

    load_stage(0, 0);
    for (int i = 0; i < 12; i++) {
        const int s = i & 1;
        if (i < 11) { load_stage(i+1, s^1); CP_WAIT1(); }
        else        { CP_WAIT0(); }
        __syncthreads();
        const uint32_t sa  = sb + s*GSTAGE;
        const uint32_t sbB = sb + 2*GSTAGE + s*GSTAGE;
        #pragma unroll
        for (int kk = 0; kk < 4; kk++) {
            uint32_t af[2][4];
            #pragma unroll
            for (int mt = 0; mt < 2; mt++) {
                int r = aRow + mt*16, c = kk*2 + aC16;
                ldmx4(af[mt], sa + r*128 + ((c ^ (r & 7))*16));
            }
            #pragma unroll
            for (int np = 0; np < 4; np++) {
                uint32_t bf[4];
                int r = bRow + np*16, c = kk*2 + bC16;
                ldmx4(bf, sbB + r*128 + ((c ^ (r & 7))*16));
                #pragma unroll
                for (int mt = 0; mt < 2; mt++) {
                    mma16816(acc[mt][np*2+0], af[mt], bf+0);
                    mma16816(acc[mt][np*2+1], af[mt], bf+2);
                }
            }
        }
        __syncthreads();
    }

    if (NOUT == 256) {
        // plain fp32 store (proj output)
        #pragma unroll
        for (int nt = 0; nt < 8; nt++) {
            int col = n0 + wn*64 + nt*8 + lc2;
            float bx = __ldg(bias + col), by = __ldg(bias + col + 1);
            #pragma unroll
            for (int mt = 0; mt < 2; mt++) {
                int row = m0 + wm*32 + mt*16 + (lane >> 2);
                float2 v0 = make_float2(acc[mt][nt][0] + bx, acc[mt][nt][1] + by);
                float2 v1 = make_float2(acc[mt][nt][2] + bx, acc[mt][nt][3] + by);
                *(float2*)(extC + (size_t)row*NOUT + col)       = v0;
                *(float2*)(extC + (size_t)(row+8)*NOUT + col)   = v1;
            }
        }
    } else {
        // KV epilogue: write formatted K / V tiles (bf16 hi/lo, swizzled)
        const bool isK = (n0 + wn*64) < 256;
        #pragma unroll
        for (int mt = 0; mt < 2; mt++) {
            int rowb = m0 + wm*32 + mt*16 + (lane >> 2);
            #pragma unroll
            for (int rr = 0; rr < 2; rr++) {
                int r = rowb + rr*8;
                int win = r / 49, tok = r - win*49;
                int tk7 = tok & 7;
                if (isK) {
                    char* base = (char*)g_Ks + (size_t)win*65536 + (size_t)tok*128;
                    #pragma unroll
                    for (int nt = 0; nt < 8; nt++) {
                        int gc = n0 + wn*64 + nt*8 + lc2;
                        float v0 = acc[mt][nt][rr*2]   + __ldg(bias + gc);
                        float v1 = acc[mt][nt][rr*2+1] + __ldg(bias + gc + 1);
                        int head = gc >> 5, d = gc & 31;
                        __nv_bfloat16 h0 = __float2bfloat16(v0), h1 = __float2bfloat16(v1);
                        __nv_bfloat16 l0 = __float2bfloat16(v0 - __bfloat162float(h0));
                        __nv_bfloat16 l1 = __float2bfloat16(v1 - __bfloat162float(h1));
                        char* tb = base + head*8192;
                        int inb = (2*d) & 15;
                        *(uint32_t*)(tb + (((d>>3)     ^ tk7)*16) + inb) = pkbf(h0, h1);
                        *(uint32_t*)(tb + (((4+(d>>3)) ^ tk7)*16) + inb) = pkbf(l0, l1);
                    }
                } else {
                    char* base = (char*)g_Vt + (size_t)win*65536;
                    int toff = tok*2, inb = toff & 15, tch = toff >> 4;
                    #pragma unroll
                    for (int nt = 0; nt < 8; nt++) {
                        int gc = n0 + wn*64 + nt*8 + lc2;
                        float v0 = acc[mt][nt][rr*2]   + __ldg(bias + gc);
                        float v1 = acc[mt][nt][rr*2+1] + __ldg(bias + gc + 1);
                        int c = gc - 256, head = c >> 5, dim = c & 31;
                        char* tb = base + head*8192;
                        #pragma unroll
                        for (int e = 0; e < 2; e++) {
                            int dm = dim + e;
                            float v = e ? v1 : v0;
                            __nv_bfloat16 hv = __float2bfloat16(v);
                            __nv_bfloat16 lv = __float2bfloat16(v - __bfloat162float(hv));
                            uint32_t off = dm*128 + ((tch ^ (dm&7))*16) + inb;
                            *(__nv_bfloat16*)(tb + off)        = hv;
                            *(__nv_bfloat16*)(tb + 4096 + off) = lv;
                        }
                    }
                }
            }
        }
    }
}

// ---------------- tensor-core attention ----------------
#define ASMEM 131072
__global__ void __launch_bounds__(256, 1)
attn_k()
{
    extern __shared__ char sm[];
    const int tid = threadIdx.x, b = blockIdx.x;
    const uint32_t sb = smem_u32(sm);

    {   // stage pre-formatted K (64KB) + V (64KB)
        const char* srcK = (const char*)g_Ks + (size_t)b*65536;
        const char* srcV = (const char*)g_Vt + (size_t)b*65536;
        #pragma unroll
        for (int u = 0; u < 16; u++) {
            int i = tid + u*256;   // 0..4095
            cp_async16(sb + i*16,         srcK + i*16);
            cp_async16(sb + 65536 + i*16, srcV + i*16);
        }
        CP_COMMIT(); CP_WAIT0();
    }
    __syncthreads();

    const int h = tid >> 5, lane = tid & 31;
    const int img = b >> 6;
    const uint32_t Kt  = sb + h*8192;
    const uint32_t Vhi = sb + 65536 + h*8192;
    const uint32_t Vlo = Vhi + 4096;
    const int lr = lane >> 2, lc2 = 2*(lane & 3);
    const int brow = (lane & 7) + ((lane >> 4) << 3);
    const int bch  = (lane >> 3) & 1;

    const uint4*  qf = g_Qf    + ((size_t)(img*HEADS + h)*16)*32 + lane;
    const float4* bf = g_biasF + ((size_t)h*4*7)*32 + lane;

    for (int mt = 0; mt < 4; mt++) {
        // Q A-fragments: kinds {Qhi d0-15, Qhi d16-31, Qlo d0-15, Qlo d16-31}
        uint32_t af[4][4];
        #pragma unroll
        for (int kd = 0; kd < 4; kd++) {
            uint4 v = __ldg(qf + (mt*4 + kd)*32);
            af[kd][0]=v.x; af[kd][1]=v.y; af[kd][2]=v.z; af[kd][3]=v.w;
        }
        // QK^T: s[ntile][4]; ntile 7 computed but unused (K pad rows are zero)
        float s[8][4];
        #pragma unroll
        for (int nt = 0; nt < 8; nt++)
            #pragma unroll
            for (int j = 0; j < 4; j++) s[nt][j] = 0.f;

        #pragma unroll
        for (int np = 0; np < 4; np++) {
            uint32_t kb[4][4];
            int row = np*16 + brow;
            #pragma unroll
            for (int ch = 0; ch < 4; ch++) {
                int chunk = ch*2 + bch;
                ldmx4(kb[ch], Kt + row*128 + ((chunk ^ (row & 7))*16));
            }
            float* s0 = s[2*np]; float* s1 = s[2*np+1];
            mma16816(s0, af[0], kb[0]+0); mma16816(s1, af[0], kb[0]+2);
            mma16816(s0, af[1], kb[1]+0); mma16816(s1, af[1], kb[1]+2);
            mma16816(s0, af[2], kb[0]+0); mma16816(s1, af[2], kb[0]+2);
            mma16816(s0, af[3], kb[1]+0); mma16816(s1, af[3], kb[1]+2);
            mma16816(s0, af[0], kb[2]+0); mma16816(s1, af[0], kb[2]+2);
            mma16816(s0, af[1], kb[3]+0); mma16816(s1, af[1], kb[3]+2);
        }

        // bias (+mask) and softmax over ntiles 0..6
        float mx0 = -1e30f, mx1 = -1e30f;
        #pragma unroll
        for (int nt = 0; nt < 7; nt++) {
            float4 t = __ldg(bf + (mt*7 + nt)*32);
            s[nt][0] += t.x; s[nt][1] += t.y; s[nt][2] += t.z; s[nt][3] += t.w;
            mx0 = fmaxf(mx0, fmaxf(s[nt][0], s[nt][1]));
            mx1 = fmaxf(mx1, fmaxf(s[nt][2], s[nt][3]));
        }
        mx0 = fmaxf(mx0, __shfl_xor_sync(0xFFFFFFFF, mx0, 1));
        mx0 = fmaxf(mx0, __shfl_xor_sync(0xFFFFFFFF, mx0, 2));
        mx1 = fmaxf(mx1, __shfl_xor_sync(0xFFFFFFFF, mx1, 1));
        mx1 = fmaxf(mx1, __shfl_xor_sync(0xFFFFFFFF, mx1, 2));
        float den0 = 0.f, den1 = 0.f;
        #pragma unroll
        for (int nt = 0; nt < 7; nt++) {
            s[nt][0] = __expf(s[nt][0] - mx0); den0 += s[nt][0];
            s[nt][1] = __expf(s[nt][1] - mx0); den0 += s[nt][1];
            s[nt][2] = __expf(s[nt][2] - mx1); den1 += s[nt][2];
            s[nt][3] = __expf(s[nt][3] - mx1); den1 += s[nt][3];
        }
        den0 += __shfl_xor_sync(0xFFFFFFFF, den0, 1);
        den0 += __shfl_xor_sync(0xFFFFFFFF, den0, 2);
        den1 += __shfl_xor_sync(0xFFFFFFFF, den1, 1);
        den1 += __shfl_xor_sync(0xFFFFFFFF, den1, 2);
        float rinv0 = 1.f / den0, rinv1 = 1.f / den1;

        // P -> A fragments (hi/lo bf16), k = tokens
        uint32_t ph[4][4], pl[4][4];
        #pragma unroll
        for (int ks = 0; ks < 4; ks++) {
            #pragma unroll
            for (int half = 0; half < 2; half++) {      // ntile 2ks, 2ks+1
                int nt = 2*ks + half;
                if (nt < 7) {
                    #pragma unroll
                    for (int pr = 0; pr < 2; pr++) {    // (c0,c1) then (c2,c3)
                        float p0 = s[nt][pr*2], p1 = s[nt][pr*2+1];
                        __nv_bfloat16 h0 = __float2bfloat16(p0), h1 = __float2bfloat16(p1);
                        __nv_bfloat16 q0 = __float2bfloat16(p0 - __bfloat162float(h0));
                        __nv_bfloat16 q1 = __float2bfloat16(p1 - __bfloat162float(h1));
                        ph[ks][half*2+pr] = pkbf(h0, h1);
                        pl[ks][half*2+pr] = pkbf(q0, q1);
                    }
                } else {
                    ph[ks][half*2] = 0; ph[ks][half*2+1] = 0;
                    pl[ks][half*2] = 0; pl[ks][half*2+1] = 0;
                }
            }
        }

        // PV: out[dim-ntile 4][4]
        float o[4][4];
        #pragma unroll
        for (int nt = 0; nt < 4; nt++)
            #pragma unroll
            for (int j = 0; j < 4; j++) o[nt][j] = 0.f;
        #pragma unroll
        for (int ks = 0; ks < 4; ks++) {
            #pragma unroll
            for (int nh = 0; nh < 2; nh++) {
                uint32_t vh[4], vl[4];
                int row = nh*16 + brow;
                int chunk = ks*2 + bch;
                uint32_t swoff = (uint32_t)(row*128 + ((chunk ^ (row & 7))*16));
                ldmx4(vh, Vhi + swoff);
                ldmx4(vl, Vlo + swoff);
                float* o0 = o[2*nh]; float* o1 = o[2*nh+1];
                mma16816(o0, ph[ks], vh+0); mma16816(o1, ph[ks], vh+2);
                mma16816(o0, pl[ks], vh+0); mma16816(o1, pl[ks], vh+2);
                mma16816(o0, ph[ks], vl+0); mma16816(o1, ph[ks], vl+2);
            }
        }

        // store to g_A2 (hi | lo split, [t][512])
        int r0 = mt*16 + lr, r1 = r0 + 8;
        if (r0 < 49) {
            __nv_bfloat16* dst = g_A2 + ((size_t)b*NTOK + r0)*KDA;
            #pragma unroll
            for (int nt = 0; nt < 4; nt++) {
                int gc = h*HDIM + nt*8 + lc2;
                float v0 = o[nt][0]*rinv0, v1 = o[nt][1]*rinv0;
                __nv_bfloat16 h0 = __float2bfloat16(v0), h1 = __float2bfloat16(v1);
                __nv_bfloat16 l0 = __float2bfloat16(v0 - __bfloat162float(h0));
                __nv_bfloat16 l1 = __float2bfloat16(v1 - __bfloat162float(h1));
                *(uint32_t*)(dst + gc)       = pkbf(h0, h1);
                *(uint32_t*)(dst + 256 + gc) = pkbf(l0, l1);
            }
        }
        if (r1 < 49) {
            __nv_bfloat16* dst = g_A2 + ((size_t)b*NTOK + r1)*KDA;
            #pragma unroll
            for (int nt = 0; nt < 4; nt++) {
                int gc = h*HDIM + nt*8 + lc2;
                float v0 = o[nt][2]*rinv1, v1 = o[nt][3]*rinv1;
                __nv_bfloat16 h0 = __float2bfloat16(v0), h1 = __float2bfloat16(v1);
                __nv_bfloat16 l0 = __float2bfloat16(v0 - __bfloat162float(h0));
                __nv_bfloat16 l1 = __float2bfloat16(v1 - __bfloat162float(h1));
                *(uint32_t*)(dst + gc)       = pkbf(h0, h1);
                *(uint32_t*)(dst + 256 + gc) = pkbf(l0, l1);
            }
        }
    }
}

// ---------------- launch ----------------
extern "C" void kernel_launch(void* const* d_in, const int* in_sizes, int n_in,
                              void* d_out, int out_size)
{
    const float* x      = (const float*)d_in[0];
    const float* qg     = (const float*)d_in[1];
    const float* qkv_w  = (const float*)d_in[2];
    const float* qkv_b  = (const float*)d_in[3];
    const float* proj_w = (const float*)d_in[4];
    const float* proj_b = (const float*)d_in[5];
    const float* rbt    = (const float*)d_in[6];
    float* out = (float*)d_out;
    (void)in_sizes; (void)n_in; (void)out_size;

    cudaFuncSetAttribute(gemm_k<512>, cudaFuncAttributeMaxDynamicSharedMemorySize, GSMEM);
    cudaFuncSetAttribute(gemm_k<256>, cudaFuncAttributeMaxDynamicSharedMemorySize, GSMEM);
    cudaFuncSetAttribute(attn_k,      cudaFuncAttributeMaxDynamicSharedMemorySize, ASMEM);

    prep_w<<<1536, 256>>>(qkv_w, proj_w, rbt);
    prep_q<<<1024, 256>>>(qg);
    conv_x<<<TOKS, 256>>>(x);
    {
        dim3 g1(TOKS/128, 4);
        gemm_k<512><<<g1, 256, GSMEM>>>(qkv_b, nullptr);
    }
    attn_k<<<BWIN, 256, ASMEM>>>();
    {
        dim3 g2(TOKS/128, 2);
        gemm_k<256><<<g2, 256, GSMEM>>>(proj_b, out);
    }
}

// round 6
// speedup vs baseline: 1.3489x; 1.0935x over previous
#include <cuda_runtime.h>
#include <cuda_bf16.h>
#include <cstdint>
#include <math.h>

#define NTOK   49
#define CDIM   256
#define HEADS  8
#define HDIM   32
#define BWIN   4096
#define TOKS   (BWIN*NTOK)          // 200704 = 1568 * 128
#define KDA    512                  // A storage: hi | lo
#define KDB    768                  // B storage: hi | hi | lo
#define SCALE  0.17677669529663688f

// ---------------- scratch (device globals; no allocs) ----------------
__device__ __nv_bfloat16 g_A1[(size_t)TOKS*KDA];  // x split   [t][512]
__device__ __nv_bfloat16 g_A2[(size_t)TOKS*KDA];  // attn-out split
__device__ __nv_bfloat16 g_B1[512*KDB];           // qkv_w split  [n][768]
__device__ __nv_bfloat16 g_B2[256*KDB];           // proj_w split
// K tiles: [win][head] 64 tok-rows x 128B (32 bf16 hi | 32 lo), swizzled. pads stay 0.
__device__ unsigned char g_Ks[(size_t)BWIN*HEADS*8192];
// V tiles: [win][head] { hi: 32 dim-rows x 128B (64 tok bf16) ; lo same } = 8KB. pads stay 0.
__device__ unsigned char g_Vt[(size_t)BWIN*HEADS*8192];
// Q fragments: [img][head][mtile 4][kind 4][lane 32] uint4 (a0..a3 bf16x2)
__device__ uint4  g_Qf[64*HEADS*4*4*32];
// bias in C-fragment layout, mask folded: [head][mtile 4][ntile 7][lane 32] float4
__device__ float4 g_biasF[HEADS*4*7*32];

// ---------------- helpers ----------------
__device__ __forceinline__ uint32_t smem_u32(const void* p){
    uint32_t a;
    asm("{ .reg .u64 t; cvta.to.shared.u64 t, %1; cvt.u32.u64 %0, t; }" : "=r"(a) : "l"(p));
    return a;
}
__device__ __forceinline__ void cp_async16(uint32_t dst, const void* src){
    asm volatile("cp.async.cg.shared.global [%0], [%1], 16;" :: "r"(dst), "l"(src));
}
#define CP_COMMIT() asm volatile("cp.async.commit_group;")
#define CP_WAIT1()  asm volatile("cp.async.wait_group 1;")
#define CP_WAIT0()  asm volatile("cp.async.wait_group 0;")

__device__ __forceinline__ void ldmx4(uint32_t* r, uint32_t addr){
    asm volatile("ldmatrix.sync.aligned.m8n8.x4.shared.b16 {%0,%1,%2,%3}, [%4];"
        : "=r"(r[0]), "=r"(r[1]), "=r"(r[2]), "=r"(r[3]) : "r"(addr));
}
__device__ __forceinline__ void mma16816(float* c, const uint32_t* a, const uint32_t* b){
    asm volatile("mma.sync.aligned.m16n8k16.row.col.f32.bf16.bf16.f32 "
        "{%0,%1,%2,%3}, {%4,%5,%6,%7}, {%8,%9}, {%0,%1,%2,%3};"
        : "+f"(c[0]), "+f"(c[1]), "+f"(c[2]), "+f"(c[3])
        : "r"(a[0]), "r"(a[1]), "r"(a[2]), "r"(a[3]), "r"(b[0]), "r"(b[1]));
}
__device__ __forceinline__ uint32_t pkbf(__nv_bfloat16 a, __nv_bfloat16 b){
    return (uint32_t)__bfloat16_as_ushort(a) | ((uint32_t)__bfloat16_as_ushort(b) << 16);
}
__device__ __forceinline__ int rpi(int r, int c){
    int ai = r/7, aj = r%7, bi = c/7, bj = c%7;
    return (ai - bi + 6)*13 + (aj - bj + 6);
}

// ---------------- prep: weights split, bias fragments ----------------
__global__ void prep_w(const float* __restrict__ qkv_w,
                       const float* __restrict__ proj_w,
                       const float* __restrict__ rbt)
{
    int idx = blockIdx.x * 256 + threadIdx.x;   // 1536*256 = 393216
    if (idx < 512*768) {
        int j = idx / 768, c = idx % 768;
        int cc = c & 255, sect = c >> 8;
        float wv = qkv_w[j*256 + cc];
        __nv_bfloat16 hi = __float2bfloat16(wv);
        g_B1[idx] = (sect < 2) ? hi : __float2bfloat16(wv - __bfloat162float(hi));
    }
    if (idx < 256*768) {
        int j = idx / 768, c = idx % 768;
        int cc = c & 255, sect = c >> 8;
        float wv = proj_w[j*256 + cc];
        __nv_bfloat16 hi = __float2bfloat16(wv);
        g_B2[idx] = (sect < 2) ? hi : __float2bfloat16(wv - __bfloat162float(hi));
    }
    if (idx < HEADS*4*7*32) {
        int lane = idx & 31;
        int nt = (idx >> 5) % 7;
        int mt = (idx >> 5) / 7 % 4;
        int h  = idx / (32*7*4);
        int r0 = mt*16 + (lane>>2), r1 = r0 + 8;
        int c0 = nt*8 + 2*(lane&3), c1 = c0 + 1;
        float4 v;
        v.x = (r0 < 49 && c0 < 49) ? rbt[rpi(r0,c0)*HEADS + h] : -1e30f;
        v.y = (r0 < 49 && c1 < 49) ? rbt[rpi(r0,c1)*HEADS + h] : -1e30f;
        v.z = (r1 < 49 && c0 < 49) ? rbt[rpi(r1,c0)*HEADS + h] : -1e30f;
        v.w = (r1 < 49 && c1 < 49) ? rbt[rpi(r1,c1)*HEADS + h] : -1e30f;
        g_biasF[idx] = v;
    }
}

// ---------------- prep: Q -> A-fragments (scaled, hi/lo split) ----------------
__global__ void prep_q(const float* __restrict__ qg)
{
    int idx = blockIdx.x * 256 + threadIdx.x;   // 1024*256 = 262144
    int lane = idx & 31;
    int kind = (idx >> 5) & 3;
    int mt   = (idx >> 7) & 3;
    int h    = (idx >> 9) & 7;
    int img  = idx >> 12;
    int r = mt*16 + (lane>>2);
    int c2 = 2*(lane&3);
    int db = (kind & 1) * 16;     // dim block
    bool lo = kind >= 2;

    auto qget = [&](int rr, int d) -> __nv_bfloat16 {
        if (rr >= 49) return __float2bfloat16(0.f);
        float v = qg[(((size_t)img*HEADS + h)*NTOK + rr)*HDIM + d] * SCALE;
        __nv_bfloat16 hv = __float2bfloat16(v);
        if (!lo) return hv;
        return __float2bfloat16(v - __bfloat162float(hv));
    };
    uint4 o;
    o.x = pkbf(qget(r,   db+c2),   qget(r,   db+c2+1));
    o.y = pkbf(qget(r+8, db+c2),   qget(r+8, db+c2+1));
    o.z = pkbf(qget(r,   db+c2+8), qget(r,   db+c2+9));
    o.w = pkbf(qget(r+8, db+c2+8), qget(r+8, db+c2+9));
    g_Qf[idx] = o;
}

// ---------------- convert x -> A1 (hi|lo) ----------------
__global__ void conv_x(const float* __restrict__ x)
{
    size_t t = blockIdx.x;
    int c = threadIdx.x;
    float v = x[t*CDIM + c];
    __nv_bfloat16 hi = __float2bfloat16(v);
    __nv_bfloat16 lo = __float2bfloat16(v - __bfloat162float(hi));
    size_t rb = t * KDA;
    g_A1[rb + c]       = hi;
    g_A1[rb + 256 + c] = lo;
}

// ---------------- mma.sync bf16 GEMM: C[128,128] per CTA, K'=768 ----------------
// 3-stage cp.async pipeline, one __syncthreads per K-iteration.
// Stage s occupies [s*32KB, s*32KB+16KB) = A, [+16KB, +32KB) = B.
#define GSTAGE 16384
#define GSMEM  (3*2*GSTAGE)    // 96 KB

template<int NOUT>
__global__ void __launch_bounds__(256, 2)
gemm_k(const float* __restrict__ bias, float* __restrict__ extC)
{
    extern __shared__ char sm[];
    const __nv_bfloat16* Ag = (NOUT == 512) ? g_A1 : g_A2;
    const __nv_bfloat16* Bg = (NOUT == 512) ? g_B1 : g_B2;

    const int tid = threadIdx.x;
    const int n0 = blockIdx.x * 128;   // n fastest: CTAs sharing A run together
    const int m0 = blockIdx.y * 128;
    const uint32_t sb = smem_u32(sm);

    auto load_stage = [&](int i, int s){
        int aoff = (i < 8) ? i*64 : (i-8)*64;
        const char* Abase = (const char*)Ag + ((size_t)m0*KDA + (size_t)aoff)*2;
        const char* Bbase = (const char*)Bg + ((size_t)n0*KDB + (size_t)i*64)*2;
        uint32_t sa  = sb + s*2*GSTAGE;
        uint32_t sbB = sa + GSTAGE;
        #pragma unroll
        for (int u = 0; u < 4; u++) {
            int idx = tid + u*256;
            int r = idx >> 3, c16 = idx & 7;
            uint32_t dst = (uint32_t)(r*128 + ((c16 ^ (r & 7))*16));
            cp_async16(sa  + dst, Abase + (size_t)r*(KDA*2) + c16*16);
            cp_async16(sbB + dst, Bbase + (size_t)r*(KDB*2) + c16*16);
        }
        CP_COMMIT();
    };

    const int w = tid >> 5, lane = tid & 31;
    const int wm = w >> 1, wn = w & 1;
    const int aRow = wm*32 + (lane & 15);
    const int aC16 = (lane >> 4);
    const int bRow = wn*64 + (lane & 7) + ((lane >> 4) << 3);
    const int bC16 = (lane >> 3) & 1;
    const int lc2 = 2*(lane & 3);

    float acc[2][8][4];
    #pragma unroll
    for (int mt = 0; mt < 2; mt++)
        #pragma unroll
        for (int nt = 0; nt < 8; nt++)
            #pragma unroll
            for (int q = 0; q < 4; q++) acc[mt][nt][q] = 0.f;

    load_stage(0, 0);
    load_stage(1, 1);
    int s = 0;
    for (int i = 0; i < 12; i++) {
        if (i < 11) { CP_WAIT1(); } else { CP_WAIT0(); }
        __syncthreads();
        if (i + 2 < 12) {
            int s2 = s + 2; if (s2 >= 3) s2 -= 3;
            load_stage(i + 2, s2);
        }
        const uint32_t sa  = sb + s*2*GSTAGE;
        const uint32_t sbB = sa + GSTAGE;
        #pragma unroll
        for (int kk = 0; kk < 4; kk++) {
            uint32_t af[2][4];
            #pragma unroll
            for (int mt = 0; mt < 2; mt++) {
                int r = aRow + mt*16, c = kk*2 + aC16;
                ldmx4(af[mt], sa + r*128 + ((c ^ (r & 7))*16));
            }
            #pragma unroll
            for (int np = 0; np < 4; np++) {
                uint32_t bf[4];
                int r = bRow + np*16, c = kk*2 + bC16;
                ldmx4(bf, sbB + r*128 + ((c ^ (r & 7))*16));
                #pragma unroll
                for (int mt = 0; mt < 2; mt++) {
                    mma16816(acc[mt][np*2+0], af[mt], bf+0);
                    mma16816(acc[mt][np*2+1], af[mt], bf+2);
                }
            }
        }
        if (++s >= 3) s -= 3;
    }

    if (NOUT == 256) {
        // plain fp32 store (proj output)
        #pragma unroll
        for (int nt = 0; nt < 8; nt++) {
            int col = n0 + wn*64 + nt*8 + lc2;
            float bx = __ldg(bias + col), by = __ldg(bias + col + 1);
            #pragma unroll
            for (int mt = 0; mt < 2; mt++) {
                int row = m0 + wm*32 + mt*16 + (lane >> 2);
                float2 v0 = make_float2(acc[mt][nt][0] + bx, acc[mt][nt][1] + by);
                float2 v1 = make_float2(acc[mt][nt][2] + bx, acc[mt][nt][3] + by);
                *(float2*)(extC + (size_t)row*NOUT + col)       = v0;
                *(float2*)(extC + (size_t)(row+8)*NOUT + col)   = v1;
            }
        }
    } else {
        // KV epilogue: write formatted K / V tiles (bf16 hi/lo, swizzled)
        const bool isK = (n0 + wn*64) < 256;
        #pragma unroll
        for (int mt = 0; mt < 2; mt++) {
            int rowb = m0 + wm*32 + mt*16 + (lane >> 2);
            #pragma unroll
            for (int rr = 0; rr < 2; rr++) {
                int r = rowb + rr*8;
                int win = r / 49, tok = r - win*49;
                int tk7 = tok & 7;
                if (isK) {
                    char* base = (char*)g_Ks + (size_t)win*65536 + (size_t)tok*128;
                    #pragma unroll
                    for (int nt = 0; nt < 8; nt++) {
                        int gc = n0 + wn*64 + nt*8 + lc2;
                        float v0 = acc[mt][nt][rr*2]   + __ldg(bias + gc);
                        float v1 = acc[mt][nt][rr*2+1] + __ldg(bias + gc + 1);
                        int head = gc >> 5, d = gc & 31;
                        __nv_bfloat16 h0 = __float2bfloat16(v0), h1 = __float2bfloat16(v1);
                        __nv_bfloat16 l0 = __float2bfloat16(v0 - __bfloat162float(h0));
                        __nv_bfloat16 l1 = __float2bfloat16(v1 - __bfloat162float(h1));
                        char* tb = base + head*8192;
                        int inb = (2*d) & 15;
                        *(uint32_t*)(tb + (((d>>3)     ^ tk7)*16) + inb) = pkbf(h0, h1);
                        *(uint32_t*)(tb + (((4+(d>>3)) ^ tk7)*16) + inb) = pkbf(l0, l1);
                    }
                } else {
                    char* base = (char*)g_Vt + (size_t)win*65536;
                    int toff = tok*2, inb = toff & 15, tch = toff >> 4;
                    #pragma unroll
                    for (int nt = 0; nt < 8; nt++) {
                        int gc = n0 + wn*64 + nt*8 + lc2;
                        float v0 = acc[mt][nt][rr*2]   + __ldg(bias + gc);
                        float v1 = acc[mt][nt][rr*2+1] + __ldg(bias + gc + 1);
                        int c = gc - 256, head = c >> 5, dim = c & 31;
                        char* tb = base + head*8192;
                        #pragma unroll
                        for (int e = 0; e < 2; e++) {
                            int dm = dim + e;
                            float v = e ? v1 : v0;
                            __nv_bfloat16 hv = __float2bfloat16(v);
                            __nv_bfloat16 lv = __float2bfloat16(v - __bfloat162float(hv));
                            uint32_t off = dm*128 + ((tch ^ (dm&7))*16) + inb;
                            *(__nv_bfloat16*)(tb + off)        = hv;
                            *(__nv_bfloat16*)(tb + 4096 + off) = lv;
                        }
                    }
                }
            }
        }
    }
}

// ---------------- tensor-core attention ----------------
#define ASMEM 131072
__global__ void __launch_bounds__(256, 1)
attn_k()
{
    extern __shared__ char sm[];
    const int tid = threadIdx.x, b = blockIdx.x;
    const uint32_t sb = smem_u32(sm);

    {   // stage pre-formatted K (64KB) + V (64KB)
        const char* srcK = (const char*)g_Ks + (size_t)b*65536;
        const char* srcV = (const char*)g_Vt + (size_t)b*65536;
        #pragma unroll
        for (int u = 0; u < 16; u++) {
            int i = tid + u*256;   // 0..4095
            cp_async16(sb + i*16,         srcK + i*16);
            cp_async16(sb + 65536 + i*16, srcV + i*16);
        }
        CP_COMMIT(); CP_WAIT0();
    }
    __syncthreads();

    const int h = tid >> 5, lane = tid & 31;
    const int img = b >> 6;
    const uint32_t Kt  = sb + h*8192;
    const uint32_t Vhi = sb + 65536 + h*8192;
    const uint32_t Vlo = Vhi + 4096;
    const int lr = lane >> 2, lc2 = 2*(lane & 3);
    const int brow = (lane & 7) + ((lane >> 4) << 3);
    const int bch  = (lane >> 3) & 1;

    const uint4*  qf = g_Qf    + ((size_t)(img*HEADS + h)*16)*32 + lane;
    const float4* bf = g_biasF + ((size_t)h*4*7)*32 + lane;

    for (int mt = 0; mt < 4; mt++) {
        // Q A-fragments: kinds {Qhi d0-15, Qhi d16-31, Qlo d0-15, Qlo d16-31}
        uint32_t af[4][4];
        #pragma unroll
        for (int kd = 0; kd < 4; kd++) {
            uint4 v = __ldg(qf + (mt*4 + kd)*32);
            af[kd][0]=v.x; af[kd][1]=v.y; af[kd][2]=v.z; af[kd][3]=v.w;
        }
        // QK^T: s[ntile][4]; ntile 7 computed but unused (K pad rows are zero)
        float s[8][4];
        #pragma unroll
        for (int nt = 0; nt < 8; nt++)
            #pragma unroll
            for (int j = 0; j < 4; j++) s[nt][j] = 0.f;

        #pragma unroll
        for (int np = 0; np < 4; np++) {
            uint32_t kb[4][4];
            int row = np*16 + brow;
            #pragma unroll
            for (int ch = 0; ch < 4; ch++) {
                int chunk = ch*2 + bch;
                ldmx4(kb[ch], Kt + row*128 + ((chunk ^ (row & 7))*16));
            }
            float* s0 = s[2*np]; float* s1 = s[2*np+1];
            mma16816(s0, af[0], kb[0]+0); mma16816(s1, af[0], kb[0]+2);
            mma16816(s0, af[1], kb[1]+0); mma16816(s1, af[1], kb[1]+2);
            mma16816(s0, af[2], kb[0]+0); mma16816(s1, af[2], kb[0]+2);
            mma16816(s0, af[3], kb[1]+0); mma16816(s1, af[3], kb[1]+2);
            mma16816(s0, af[0], kb[2]+0); mma16816(s1, af[0], kb[2]+2);
            mma16816(s0, af[1], kb[3]+0); mma16816(s1, af[1], kb[3]+2);
        }

        // bias (+mask) and softmax over ntiles 0..6
        float mx0 = -1e30f, mx1 = -1e30f;
        #pragma unroll
        for (int nt = 0; nt < 7; nt++) {
            float4 t = __ldg(bf + (mt*7 + nt)*32);
            s[nt][0] += t.x; s[nt][1] += t.y; s[nt][2] += t.z; s[nt][3] += t.w;
            mx0 = fmaxf(mx0, fmaxf(s[nt][0], s[nt][1]));
            mx1 = fmaxf(mx1, fmaxf(s[nt][2], s[nt][3]));
        }
        mx0 = fmaxf(mx0, __shfl_xor_sync(0xFFFFFFFF, mx0, 1));
        mx0 = fmaxf(mx0, __shfl_xor_sync(0xFFFFFFFF, mx0, 2));
        mx1 = fmaxf(mx1, __shfl_xor_sync(0xFFFFFFFF, mx1, 1));
        mx1 = fmaxf(mx1, __shfl_xor_sync(0xFFFFFFFF, mx1, 2));
        float den0 = 0.f, den1 = 0.f;
        #pragma unroll
        for (int nt = 0; nt < 7; nt++) {
            s[nt][0] = __expf(s[nt][0] - mx0); den0 += s[nt][0];
            s[nt][1] = __expf(s[nt][1] - mx0); den0 += s[nt][1];
            s[nt][2] = __expf(s[nt][2] - mx1); den1 += s[nt][2];
            s[nt][3] = __expf(s[nt][3] - mx1); den1 += s[nt][3];
        }
        den0 += __shfl_xor_sync(0xFFFFFFFF, den0, 1);
        den0 += __shfl_xor_sync(0xFFFFFFFF, den0, 2);
        den1 += __shfl_xor_sync(0xFFFFFFFF, den1, 1);
        den1 += __shfl_xor_sync(0xFFFFFFFF, den1, 2);
        float rinv0 = 1.f / den0, rinv1 = 1.f / den1;

        // P -> A fragments (hi/lo bf16), k = tokens
        uint32_t ph[4][4], pl[4][4];
        #pragma unroll
        for (int ks = 0; ks < 4; ks++) {
            #pragma unroll
            for (int half = 0; half < 2; half++) {      // ntile 2ks, 2ks+1
                int nt = 2*ks + half;
                if (nt < 7) {
                    #pragma unroll
                    for (int pr = 0; pr < 2; pr++) {    // (c0,c1) then (c2,c3)
                        float p0 = s[nt][pr*2], p1 = s[nt][pr*2+1];
                        __nv_bfloat16 h0 = __float2bfloat16(p0), h1 = __float2bfloat16(p1);
                        __nv_bfloat16 q0 = __float2bfloat16(p0 - __bfloat162float(h0));
                        __nv_bfloat16 q1 = __float2bfloat16(p1 - __bfloat162float(h1));
                        ph[ks][half*2+pr] = pkbf(h0, h1);
                        pl[ks][half*2+pr] = pkbf(q0, q1);
                    }
                } else {
                    ph[ks][half*2] = 0; ph[ks][half*2+1] = 0;
                    pl[ks][half*2] = 0; pl[ks][half*2+1] = 0;
                }
            }
        }

        // PV: out[dim-ntile 4][4]
        float o[4][4];
        #pragma unroll
        for (int nt = 0; nt < 4; nt++)
            #pragma unroll
            for (int j = 0; j < 4; j++) o[nt][j] = 0.f;
        #pragma unroll
        for (int ks = 0; ks < 4; ks++) {
            #pragma unroll
            for (int nh = 0; nh < 2; nh++) {
                uint32_t vh[4], vl[4];
                int row = nh*16 + brow;
                int chunk = ks*2 + bch;
                uint32_t swoff = (uint32_t)(row*128 + ((chunk ^ (row & 7))*16));
                ldmx4(vh, Vhi + swoff);
                ldmx4(vl, Vlo + swoff);
                float* o0 = o[2*nh]; float* o1 = o[2*nh+1];
                mma16816(o0, ph[ks], vh+0); mma16816(o1, ph[ks], vh+2);
                mma16816(o0, pl[ks], vh+0); mma16816(o1, pl[ks], vh+2);
                mma16816(o0, ph[ks], vl+0); mma16816(o1, ph[ks], vl+2);
            }
        }

        // store to g_A2 (hi | lo split, [t][512])
        int r0 = mt*16 + lr, r1 = r0 + 8;
        if (r0 < 49) {
            __nv_bfloat16* dst = g_A2 + ((size_t)b*NTOK + r0)*KDA;
            #pragma unroll
            for (int nt = 0; nt < 4; nt++) {
                int gc = h*HDIM + nt*8 + lc2;
                float v0 = o[nt][0]*rinv0, v1 = o[nt][1]*rinv0;
                __nv_bfloat16 h0 = __float2bfloat16(v0), h1 = __float2bfloat16(v1);
                __nv_bfloat16 l0 = __float2bfloat16(v0 - __bfloat162float(h0));
                __nv_bfloat16 l1 = __float2bfloat16(v1 - __bfloat162float(h1));
                *(uint32_t*)(dst + gc)       = pkbf(h0, h1);
                *(uint32_t*)(dst + 256 + gc) = pkbf(l0, l1);
            }
        }
        if (r1 < 49) {
            __nv_bfloat16* dst = g_A2 + ((size_t)b*NTOK + r1)*KDA;
            #pragma unroll
            for (int nt = 0; nt < 4; nt++) {
                int gc = h*HDIM + nt*8 + lc2;
                float v0 = o[nt][2]*rinv1, v1 = o[nt][3]*rinv1;
                __nv_bfloat16 h0 = __float2bfloat16(v0), h1 = __float2bfloat16(v1);
                __nv_bfloat16 l0 = __float2bfloat16(v0 - __bfloat162float(h0));
                __nv_bfloat16 l1 = __float2bfloat16(v1 - __bfloat162float(h1));
                *(uint32_t*)(dst + gc)       = pkbf(h0, h1);
                *(uint32_t*)(dst + 256 + gc) = pkbf(l0, l1);
            }
        }
    }
}

// ---------------- launch ----------------
extern "C" void kernel_launch(void* const* d_in, const int* in_sizes, int n_in,
                              void* d_out, int out_size)
{
    const float* x      = (const float*)d_in[0];
    const float* qg     = (const float*)d_in[1];
    const float* qkv_w  = (const float*)d_in[2];
    const float* qkv_b  = (const float*)d_in[3];
    const float* proj_w = (const float*)d_in[4];
    const float* proj_b = (const float*)d_in[5];
    const float* rbt    = (const float*)d_in[6];
    float* out = (float*)d_out;
    (void)in_sizes; (void)n_in; (void)out_size;

    cudaFuncSetAttribute(gemm_k<512>, cudaFuncAttributeMaxDynamicSharedMemorySize, GSMEM);
    cudaFuncSetAttribute(gemm_k<256>, cudaFuncAttributeMaxDynamicSharedMemorySize, GSMEM);
    cudaFuncSetAttribute(attn_k,      cudaFuncAttributeMaxDynamicSharedMemorySize, ASMEM);

    prep_w<<<1536, 256>>>(qkv_w, proj_w, rbt);
    prep_q<<<1024, 256>>>(qg);
    conv_x<<<TOKS, 256>>>(x);
    {
        dim3 g1(4, TOKS/128);       // n fastest -> A tiles shared via L2
        gemm_k<512><<<g1, 256, GSMEM>>>(qkv_b, nullptr);
    }
    attn_k<<<BWIN, 256, ASMEM>>>();
    {
        dim3 g2(2, TOKS/128);
        gemm_k<256><<<g2, 256, GSMEM>>>(proj_b, out);
    }
}

// round 7
// speedup vs baseline: 1.8330x; 1.3589x over previous
#include <cuda_runtime.h>
#include <cuda_fp16.h>
#include <cstdint>
#include <math.h>

#define NTOK   49
#define CDIM   256
#define HEADS  8
#define HDIM   32
#define BWIN   4096
#define TOKS   (BWIN*NTOK)          // 200704 = 1568 * 128
#define KD     512                  // A: hi|lo ; B: w_hi|w_hi
#define NITER  8                    // K/64
#define SCALE  0.17677669529663688f

// ---------------- scratch (device globals; no allocs) ----------------
__device__ __half g_A1[(size_t)TOKS*KD];   // x split   [t][512]
__device__ __half g_A2[(size_t)TOKS*KD];   // attn-out split
__device__ __half g_B1[512*KD];            // qkv_w  [n][ w_hi | w_hi ]
__device__ __half g_B2[256*KD];            // proj_w [n][ w_hi | w_hi ]
// K tiles: [win][head] 64 tok-rows x 64B (32 fp16 hi), swizzle key (row>>1)&3. pads stay 0.
__device__ unsigned char g_Ks[(size_t)BWIN*HEADS*4096];
// V tiles: [win][head] { hi: 32 dim-rows x 128B (64 tok fp16) ; lo same } = 8KB. pads stay 0.
__device__ unsigned char g_Vt[(size_t)BWIN*HEADS*8192];
// Q fragments: [img][head][mtile 4][kind 4][lane 32] uint4 (hi d0-15, hi d16-31, lo d0-15, lo d16-31)
__device__ uint4  g_Qf[64*HEADS*4*4*32];
// bias in C-fragment layout, mask folded: [head][mtile 4][ntile 7][lane 32] float4
__device__ float4 g_biasF[HEADS*4*7*32];

// ---------------- helpers ----------------
__device__ __forceinline__ uint32_t smem_u32(const void* p){
    uint32_t a;
    asm("{ .reg .u64 t; cvta.to.shared.u64 t, %1; cvt.u32.u64 %0, t; }" : "=r"(a) : "l"(p));
    return a;
}
__device__ __forceinline__ void cp_async16(uint32_t dst, const void* src){
    asm volatile("cp.async.cg.shared.global [%0], [%1], 16;" :: "r"(dst), "l"(src));
}
#define CP_COMMIT() asm volatile("cp.async.commit_group;")
#define CP_WAIT1()  asm volatile("cp.async.wait_group 1;")
#define CP_WAIT0()  asm volatile("cp.async.wait_group 0;")

__device__ __forceinline__ void ldmx4(uint32_t* r, uint32_t addr){
    asm volatile("ldmatrix.sync.aligned.m8n8.x4.shared.b16 {%0,%1,%2,%3}, [%4];"
        : "=r"(r[0]), "=r"(r[1]), "=r"(r[2]), "=r"(r[3]) : "r"(addr));
}
__device__ __forceinline__ void mma16816(float* c, const uint32_t* a, const uint32_t* b){
    asm volatile("mma.sync.aligned.m16n8k16.row.col.f32.f16.f16.f32 "
        "{%0,%1,%2,%3}, {%4,%5,%6,%7}, {%8,%9}, {%0,%1,%2,%3};"
        : "+f"(c[0]), "+f"(c[1]), "+f"(c[2]), "+f"(c[3])
        : "r"(a[0]), "r"(a[1]), "r"(a[2]), "r"(a[3]), "r"(b[0]), "r"(b[1]));
}
__device__ __forceinline__ uint32_t pkh(__half a, __half b){
    return (uint32_t)__half_as_ushort(a) | ((uint32_t)__half_as_ushort(b) << 16);
}
__device__ __forceinline__ int rpi(int r, int c){
    int ai = r/7, aj = r%7, bi = c/7, bj = c%7;
    return (ai - bi + 6)*13 + (aj - bj + 6);
}

// ---------------- prep: weights (fp16 hi, duplicated), bias fragments ------
__global__ void prep_w(const float* __restrict__ qkv_w,
                       const float* __restrict__ proj_w,
                       const float* __restrict__ rbt)
{
    int idx = blockIdx.x * 256 + threadIdx.x;   // 1024*256 = 262144 = 512*512
    if (idx < 512*512) {
        int j = idx >> 9, c = idx & 511;
        g_B1[idx] = __float2half_rn(qkv_w[j*256 + (c & 255)]);
    }
    if (idx < 256*512) {
        int j = idx >> 9, c = idx & 511;
        g_B2[idx] = __float2half_rn(proj_w[j*256 + (c & 255)]);
    }
    if (idx < HEADS*4*7*32) {
        int lane = idx & 31;
        int nt = (idx >> 5) % 7;
        int mt = (idx >> 5) / 7 % 4;
        int h  = idx / (32*7*4);
        int r0 = mt*16 + (lane>>2), r1 = r0 + 8;
        int c0 = nt*8 + 2*(lane&3), c1 = c0 + 1;
        float4 v;
        v.x = (r0 < 49 && c0 < 49) ? rbt[rpi(r0,c0)*HEADS + h] : -1e30f;
        v.y = (r0 < 49 && c1 < 49) ? rbt[rpi(r0,c1)*HEADS + h] : -1e30f;
        v.z = (r1 < 49 && c0 < 49) ? rbt[rpi(r1,c0)*HEADS + h] : -1e30f;
        v.w = (r1 < 49 && c1 < 49) ? rbt[rpi(r1,c1)*HEADS + h] : -1e30f;
        g_biasF[idx] = v;
    }
}

// ---------------- prep: Q -> A-fragments (scaled, fp16 hi/lo) --------------
__global__ void prep_q(const float* __restrict__ qg)
{
    int idx = blockIdx.x * 256 + threadIdx.x;   // 1024*256 = 262144
    int lane = idx & 31;
    int kind = (idx >> 5) & 3;
    int mt   = (idx >> 7) & 3;
    int h    = (idx >> 9) & 7;
    int img  = idx >> 12;
    int r = mt*16 + (lane>>2);
    int c2 = 2*(lane&3);
    int db = (kind & 1) * 16;
    bool lo = kind >= 2;

    auto qget = [&](int rr, int d) -> __half {
        if (rr >= 49) return __float2half_rn(0.f);
        float v = qg[(((size_t)img*HEADS + h)*NTOK + rr)*HDIM + d] * SCALE;
        __half hv = __float2half_rn(v);
        if (!lo) return hv;
        return __float2half_rn(v - __half2float(hv));
    };
    uint4 o;
    o.x = pkh(qget(r,   db+c2),   qget(r,   db+c2+1));
    o.y = pkh(qget(r+8, db+c2),   qget(r+8, db+c2+1));
    o.z = pkh(qget(r,   db+c2+8), qget(r,   db+c2+9));
    o.w = pkh(qget(r+8, db+c2+8), qget(r+8, db+c2+9));
    g_Qf[idx] = o;
}

// ---------------- convert x -> A1 (fp16 hi|lo) ----------------
__global__ void conv_x(const float* __restrict__ x)
{
    size_t t = blockIdx.x;
    int c = threadIdx.x;
    float v = x[t*CDIM + c];
    __half hi = __float2half_rn(v);
    __half lo = __float2half_rn(v - __half2float(hi));
    size_t rb = t * KD;
    g_A1[rb + c]       = hi;
    g_A1[rb + 256 + c] = lo;
}

// ---------------- mma.sync fp16 GEMM: C[128,128] per CTA, K=512 ------------
#define GSTAGE 16384
#define GSMEM  (3*2*GSTAGE)    // 96 KB

template<int NOUT>
__global__ void __launch_bounds__(256, 2)
gemm_k(const float* __restrict__ bias, float* __restrict__ extC)
{
    extern __shared__ char sm[];
    const __half* Ag = (NOUT == 512) ? g_A1 : g_A2;
    const __half* Bg = (NOUT == 512) ? g_B1 : g_B2;

    const int tid = threadIdx.x;
    const int n0 = blockIdx.x * 128;
    const int m0 = blockIdx.y * 128;
    const uint32_t sb = smem_u32(sm);

    auto load_stage = [&](int i, int s){
        const char* Abase = (const char*)Ag + ((size_t)m0*KD + (size_t)i*64)*2;
        const char* Bbase = (const char*)Bg + ((size_t)n0*KD + (size_t)i*64)*2;
        uint32_t sa  = sb + s*2*GSTAGE;
        uint32_t sbB = sa + GSTAGE;
        #pragma unroll
        for (int u = 0; u < 4; u++) {
            int idx = tid + u*256;
            int r = idx >> 3, c16 = idx & 7;
            uint32_t dst = (uint32_t)(r*128 + ((c16 ^ (r & 7))*16));
            cp_async16(sa  + dst, Abase + (size_t)r*(KD*2) + c16*16);
            cp_async16(sbB + dst, Bbase + (size_t)r*(KD*2) + c16*16);
        }
        CP_COMMIT();
    };

    const int w = tid >> 5, lane = tid & 31;
    const int wm = w >> 1, wn = w & 1;
    const int aRow = wm*32 + (lane & 15);
    const int aC16 = (lane >> 4);
    const int bRow = wn*64 + (lane & 7) + ((lane >> 4) << 3);
    const int bC16 = (lane >> 3) & 1;
    const int lc2 = 2*(lane & 3);

    float acc[2][8][4];
    #pragma unroll
    for (int mt = 0; mt < 2; mt++)
        #pragma unroll
        for (int nt = 0; nt < 8; nt++)
            #pragma unroll
            for (int q = 0; q < 4; q++) acc[mt][nt][q] = 0.f;

    load_stage(0, 0);
    load_stage(1, 1);
    int s = 0;
    for (int i = 0; i < NITER; i++) {
        if (i < NITER-1) { CP_WAIT1(); } else { CP_WAIT0(); }
        __syncthreads();
        if (i + 2 < NITER) {
            int s2 = s + 2; if (s2 >= 3) s2 -= 3;
            load_stage(i + 2, s2);
        }
        const uint32_t sa  = sb + s*2*GSTAGE;
        const uint32_t sbB = sa + GSTAGE;
        #pragma unroll
        for (int kk = 0; kk < 4; kk++) {
            uint32_t af[2][4];
            #pragma unroll
            for (int mt = 0; mt < 2; mt++) {
                int r = aRow + mt*16, c = kk*2 + aC16;
                ldmx4(af[mt], sa + r*128 + ((c ^ (r & 7))*16));
            }
            #pragma unroll
            for (int np = 0; np < 4; np++) {
                uint32_t bf[4];
                int r = bRow + np*16, c = kk*2 + bC16;
                ldmx4(bf, sbB + r*128 + ((c ^ (r & 7))*16));
                #pragma unroll
                for (int mt = 0; mt < 2; mt++) {
                    mma16816(acc[mt][np*2+0], af[mt], bf+0);
                    mma16816(acc[mt][np*2+1], af[mt], bf+2);
                }
            }
        }
        if (++s >= 3) s -= 3;
    }

    if (NOUT == 256) {
        #pragma unroll
        for (int nt = 0; nt < 8; nt++) {
            int col = n0 + wn*64 + nt*8 + lc2;
            float bx = __ldg(bias + col), by = __ldg(bias + col + 1);
            #pragma unroll
            for (int mt = 0; mt < 2; mt++) {
                int row = m0 + wm*32 + mt*16 + (lane >> 2);
                float2 v0 = make_float2(acc[mt][nt][0] + bx, acc[mt][nt][1] + by);
                float2 v1 = make_float2(acc[mt][nt][2] + bx, acc[mt][nt][3] + by);
                *(float2*)(extC + (size_t)row*NOUT + col)       = v0;
                *(float2*)(extC + (size_t)(row+8)*NOUT + col)   = v1;
            }
        }
    } else {
        // KV epilogue: K hi-only (4KB tile), V hi+lo (8KB tile)
        const bool isK = (n0 + wn*64) < 256;
        #pragma unroll
        for (int mt = 0; mt < 2; mt++) {
            int rowb = m0 + wm*32 + mt*16 + (lane >> 2);
            #pragma unroll
            for (int rr = 0; rr < 2; rr++) {
                int r = rowb + rr*8;
                int win = r / 49, tok = r - win*49;
                if (isK) {
                    char* base = (char*)g_Ks + (size_t)win*(HEADS*4096) + (size_t)tok*64;
                    int key = (tok >> 1) & 3;
                    #pragma unroll
                    for (int nt = 0; nt < 8; nt++) {
                        int gc = n0 + wn*64 + nt*8 + lc2;
                        float v0 = acc[mt][nt][rr*2]   + __ldg(bias + gc);
                        float v1 = acc[mt][nt][rr*2+1] + __ldg(bias + gc + 1);
                        int head = gc >> 5, d = gc & 31;
                        char* tb = base + head*4096;
                        int chunk = d >> 3, inb = (2*d) & 15;
                        *(uint32_t*)(tb + ((chunk ^ key)*16) + inb)
                            = pkh(__float2half_rn(v0), __float2half_rn(v1));
                    }
                } else {
                    char* base = (char*)g_Vt + (size_t)win*65536;
                    int toff = tok*2, inb = toff & 15, tch = toff >> 4;
                    #pragma unroll
                    for (int nt = 0; nt < 8; nt++) {
                        int gc = n0 + wn*64 + nt*8 + lc2;
                        float v0 = acc[mt][nt][rr*2]   + __ldg(bias + gc);
                        float v1 = acc[mt][nt][rr*2+1] + __ldg(bias + gc + 1);
                        int c = gc - 256, head = c >> 5, dim = c & 31;
                        char* tb = base + head*8192;
                        #pragma unroll
                        for (int e = 0; e < 2; e++) {
                            int dm = dim + e;
                            float v = e ? v1 : v0;
                            __half hv = __float2half_rn(v);
                            __half lv = __float2half_rn(v - __half2float(hv));
                            uint32_t off = dm*128 + ((tch ^ (dm&7))*16) + inb;
                            *(__half*)(tb + off)        = hv;
                            *(__half*)(tb + 4096 + off) = lv;
                        }
                    }
                }
            }
        }
    }
}

// ---------------- tensor-core attention (fp16) ----------------
#define ASMEM (32768 + 65536)   // K 32KB + V 64KB = 96KB
__global__ void __launch_bounds__(256, 2)
attn_k()
{
    extern __shared__ char sm[];
    const int tid = threadIdx.x, b = blockIdx.x;
    const uint32_t sb = smem_u32(sm);

    {   // stage K (32KB) + V (64KB)
        const char* srcK = (const char*)g_Ks + (size_t)b*32768;
        const char* srcV = (const char*)g_Vt + (size_t)b*65536;
        #pragma unroll
        for (int u = 0; u < 8; u++) {
            int i = tid + u*256;   // 0..2047
            cp_async16(sb + i*16, srcK + i*16);
        }
        #pragma unroll
        for (int u = 0; u < 16; u++) {
            int i = tid + u*256;   // 0..4095
            cp_async16(sb + 32768 + i*16, srcV + i*16);
        }
        CP_COMMIT(); CP_WAIT0();
    }
    __syncthreads();

    const int h = tid >> 5, lane = tid & 31;
    const int img = b >> 6;
    const uint32_t Kt  = sb + h*4096;
    const uint32_t Vhi = sb + 32768 + h*8192;
    const uint32_t Vlo = Vhi + 4096;
    const int lr = lane >> 2, lc2 = 2*(lane & 3);
    const int brow = (lane & 7) + ((lane >> 4) << 3);
    const int bch  = (lane >> 3) & 1;

    const uint4*  qf = g_Qf    + ((size_t)(img*HEADS + h)*16)*32 + lane;
    const float4* bf = g_biasF + ((size_t)h*4*7)*32 + lane;

    for (int mt = 0; mt < 4; mt++) {
        uint32_t af[4][4];
        #pragma unroll
        for (int kd = 0; kd < 4; kd++) {
            uint4 v = __ldg(qf + (mt*4 + kd)*32);
            af[kd][0]=v.x; af[kd][1]=v.y; af[kd][2]=v.z; af[kd][3]=v.w;
        }
        float s[8][4];
        #pragma unroll
        for (int nt = 0; nt < 8; nt++)
            #pragma unroll
            for (int j = 0; j < 4; j++) s[nt][j] = 0.f;

        // QK^T: (q_hi + q_lo) x k_hi  -> 2 ldsm + 8 mma per np
        #pragma unroll
        for (int np = 0; np < 4; np++) {
            uint32_t kb[2][4];
            int row = np*16 + brow;
            int key = (row >> 1) & 3;
            #pragma unroll
            for (int ch = 0; ch < 2; ch++) {
                int chunk = ch*2 + bch;
                ldmx4(kb[ch], Kt + row*64 + ((chunk ^ key)*16));
            }
            float* s0 = s[2*np]; float* s1 = s[2*np+1];
            mma16816(s0, af[0], kb[0]+0); mma16816(s1, af[0], kb[0]+2);
            mma16816(s0, af[1], kb[1]+0); mma16816(s1, af[1], kb[1]+2);
            mma16816(s0, af[2], kb[0]+0); mma16816(s1, af[2], kb[0]+2);
            mma16816(s0, af[3], kb[1]+0); mma16816(s1, af[3], kb[1]+2);
        }

        // bias (+mask) and softmax over ntiles 0..6
        float mx0 = -1e30f, mx1 = -1e30f;
        #pragma unroll
        for (int nt = 0; nt < 7; nt++) {
            float4 t = __ldg(bf + (mt*7 + nt)*32);
            s[nt][0] += t.x; s[nt][1] += t.y; s[nt][2] += t.z; s[nt][3] += t.w;
            mx0 = fmaxf(mx0, fmaxf(s[nt][0], s[nt][1]));
            mx1 = fmaxf(mx1, fmaxf(s[nt][2], s[nt][3]));
        }
        mx0 = fmaxf(mx0, __shfl_xor_sync(0xFFFFFFFF, mx0, 1));
        mx0 = fmaxf(mx0, __shfl_xor_sync(0xFFFFFFFF, mx0, 2));
        mx1 = fmaxf(mx1, __shfl_xor_sync(0xFFFFFFFF, mx1, 1));
        mx1 = fmaxf(mx1, __shfl_xor_sync(0xFFFFFFFF, mx1, 2));
        float den0 = 0.f, den1 = 0.f;
        #pragma unroll
        for (int nt = 0; nt < 7; nt++) {
            s[nt][0] = __expf(s[nt][0] - mx0); den0 += s[nt][0];
            s[nt][1] = __expf(s[nt][1] - mx0); den0 += s[nt][1];
            s[nt][2] = __expf(s[nt][2] - mx1); den1 += s[nt][2];
            s[nt][3] = __expf(s[nt][3] - mx1); den1 += s[nt][3];
        }
        den0 += __shfl_xor_sync(0xFFFFFFFF, den0, 1);
        den0 += __shfl_xor_sync(0xFFFFFFFF, den0, 2);
        den1 += __shfl_xor_sync(0xFFFFFFFF, den1, 1);
        den1 += __shfl_xor_sync(0xFFFFFFFF, den1, 2);
        float rinv0 = 1.f / den0, rinv1 = 1.f / den1;

        // P -> A fragments (fp16 hi/lo)
        uint32_t ph[4][4], pl[4][4];
        #pragma unroll
        for (int ks = 0; ks < 4; ks++) {
            #pragma unroll
            for (int half_ = 0; half_ < 2; half_++) {
                int nt = 2*ks + half_;
                if (nt < 7) {
                    #pragma unroll
                    for (int pr = 0; pr < 2; pr++) {
                        float p0 = s[nt][pr*2], p1 = s[nt][pr*2+1];
                        __half h0 = __float2half_rn(p0), h1 = __float2half_rn(p1);
                        __half q0 = __float2half_rn(p0 - __half2float(h0));
                        __half q1 = __float2half_rn(p1 - __half2float(h1));
                        ph[ks][half_*2+pr] = pkh(h0, h1);
                        pl[ks][half_*2+pr] = pkh(q0, q1);
                    }
                } else {
                    ph[ks][half_*2] = 0; ph[ks][half_*2+1] = 0;
                    pl[ks][half_*2] = 0; pl[ks][half_*2+1] = 0;
                }
            }
        }

        // PV: 3-term (ph*vh + pl*vh + ph*vl)
        float o[4][4];
        #pragma unroll
        for (int nt = 0; nt < 4; nt++)
            #pragma unroll
            for (int j = 0; j < 4; j++) o[nt][j] = 0.f;
        #pragma unroll
        for (int ks = 0; ks < 4; ks++) {
            #pragma unroll
            for (int nh = 0; nh < 2; nh++) {
                uint32_t vh[4], vl[4];
                int row = nh*16 + brow;
                int chunk = ks*2 + bch;
                uint32_t swoff = (uint32_t)(row*128 + ((chunk ^ (row & 7))*16));
                ldmx4(vh, Vhi + swoff);
                ldmx4(vl, Vlo + swoff);
                float* o0 = o[2*nh]; float* o1 = o[2*nh+1];
                mma16816(o0, ph[ks], vh+0); mma16816(o1, ph[ks], vh+2);
                mma16816(o0, pl[ks], vh+0); mma16816(o1, pl[ks], vh+2);
                mma16816(o0, ph[ks], vl+0); mma16816(o1, ph[ks], vl+2);
            }
        }

        // store to g_A2 (fp16 hi | lo, [t][512])
        int r0 = mt*16 + lr, r1 = r0 + 8;
        if (r0 < 49) {
            __half* dst = g_A2 + ((size_t)b*NTOK + r0)*KD;
            #pragma unroll
            for (int nt = 0; nt < 4; nt++) {
                int gc = h*HDIM + nt*8 + lc2;
                float v0 = o[nt][0]*rinv0, v1 = o[nt][1]*rinv0;
                __half h0 = __float2half_rn(v0), h1 = __float2half_rn(v1);
                __half l0 = __float2half_rn(v0 - __half2float(h0));
                __half l1 = __float2half_rn(v1 - __half2float(h1));
                *(uint32_t*)(dst + gc)       = pkh(h0, h1);
                *(uint32_t*)(dst + 256 + gc) = pkh(l0, l1);
            }
        }
        if (r1 < 49) {
            __half* dst = g_A2 + ((size_t)b*NTOK + r1)*KD;
            #pragma unroll
            for (int nt = 0; nt < 4; nt++) {
                int gc = h*HDIM + nt*8 + lc2;
                float v0 = o[nt][2]*rinv1, v1 = o[nt][3]*rinv1;
                __half h0 = __float2half_rn(v0), h1 = __float2half_rn(v1);
                __half l0 = __float2half_rn(v0 - __half2float(h0));
                __half l1 = __float2half_rn(v1 - __half2float(h1));
                *(uint32_t*)(dst + gc)       = pkh(h0, h1);
                *(uint32_t*)(dst + 256 + gc) = pkh(l0, l1);
            }
        }
    }
}

// ---------------- launch ----------------
extern "C" void kernel_launch(void* const* d_in, const int* in_sizes, int n_in,
                              void* d_out, int out_size)
{
    const float* x      = (const float*)d_in[0];
    const float* qg     = (const float*)d_in[1];
    const float* qkv_w  = (const float*)d_in[2];
    const float* qkv_b  = (const float*)d_in[3];
    const float* proj_w = (const float*)d_in[4];
    const float* proj_b = (const float*)d_in[5];
    const float* rbt    = (const float*)d_in[6];
    float* out = (float*)d_out;
    (void)in_sizes; (void)n_in; (void)out_size;

    cudaFuncSetAttribute(gemm_k<512>, cudaFuncAttributeMaxDynamicSharedMemorySize, GSMEM);
    cudaFuncSetAttribute(gemm_k<256>, cudaFuncAttributeMaxDynamicSharedMemorySize, GSMEM);
    cudaFuncSetAttribute(attn_k,      cudaFuncAttributeMaxDynamicSharedMemorySize, ASMEM);

    prep_w<<<1024, 256>>>(qkv_w, proj_w, rbt);
    prep_q<<<1024, 256>>>(qg);
    conv_x<<<TOKS, 256>>>(x);
    {
        dim3 g1(4, TOKS/128);       // n fastest -> A tiles shared via L2
        gemm_k<512><<<g1, 256, GSMEM>>>(qkv_b, nullptr);
    }
    attn_k<<<BWIN, 256, ASMEM>>>();
    {
        dim3 g2(2, TOKS/128);
        gemm_k<256><<<g2, 256, GSMEM>>>(proj_b, out);
    }
}

// round 8
// speedup vs baseline: 2.1315x; 1.1629x over previous
#include <cuda_runtime.h>
#include <cuda_fp16.h>
#include <cstdint>
#include <math.h>

#define NTOK   49
#define CDIM   256
#define HEADS  8
#define HDIM   32
#define BWIN   4096
#define TOKS   (BWIN*NTOK)          // 200704 = 1568 * 128
#define KD     512                  // A: hi|lo ; B: w_hi|w_hi
#define NITER  8                    // K/64
#define SCALE  0.17677669529663688f

// ---------------- scratch (device globals; no allocs) ----------------
__device__ __half g_A1[(size_t)TOKS*KD];   // x split   [t][512]
__device__ __half g_A2[(size_t)TOKS*KD];   // attn-out split
__device__ __half g_B1[512*KD];            // qkv_w  [n][ w_hi | w_hi ]
__device__ __half g_B2[256*KD];            // proj_w [n][ w_hi | w_hi ]
// K tiles: [win][head] 64 tok-rows x 64B (32 fp16 hi), swizzle key (tok>>1)&3. pads stay 0.
__device__ unsigned char g_Ks[(size_t)BWIN*HEADS*4096];
// V tiles: [win][head] { hi: 64 tok-rows x 64B ; lo same } = 8KB, tok-major. pads stay 0.
__device__ unsigned char g_Vt[(size_t)BWIN*HEADS*8192];
// Q fragments: [img][head][mtile 4][kind 4][lane 32] uint4
__device__ uint4  g_Qf[64*HEADS*4*4*32];
// bias in C-fragment layout, mask folded: [head][mtile 4][ntile 7][lane 32] float4
__device__ float4 g_biasF[HEADS*4*7*32];

// ---------------- helpers ----------------
__device__ __forceinline__ uint32_t smem_u32(const void* p){
    uint32_t a;
    asm("{ .reg .u64 t; cvta.to.shared.u64 t, %1; cvt.u32.u64 %0, t; }" : "=r"(a) : "l"(p));
    return a;
}
__device__ __forceinline__ void cp_async16(uint32_t dst, const void* src){
    asm volatile("cp.async.cg.shared.global [%0], [%1], 16;" :: "r"(dst), "l"(src));
}
#define CP_COMMIT() asm volatile("cp.async.commit_group;")
#define CP_WAIT1()  asm volatile("cp.async.wait_group 1;")
#define CP_WAIT0()  asm volatile("cp.async.wait_group 0;")

__device__ __forceinline__ void ldmx4(uint32_t* r, uint32_t addr){
    asm volatile("ldmatrix.sync.aligned.m8n8.x4.shared.b16 {%0,%1,%2,%3}, [%4];"
        : "=r"(r[0]), "=r"(r[1]), "=r"(r[2]), "=r"(r[3]) : "r"(addr));
}
__device__ __forceinline__ void ldmx4t(uint32_t* r, uint32_t addr){
    asm volatile("ldmatrix.sync.aligned.m8n8.x4.trans.shared.b16 {%0,%1,%2,%3}, [%4];"
        : "=r"(r[0]), "=r"(r[1]), "=r"(r[2]), "=r"(r[3]) : "r"(addr));
}
__device__ __forceinline__ void mma16816(float* c, const uint32_t* a, const uint32_t* b){
    asm volatile("mma.sync.aligned.m16n8k16.row.col.f32.f16.f16.f32 "
        "{%0,%1,%2,%3}, {%4,%5,%6,%7}, {%8,%9}, {%0,%1,%2,%3};"
        : "+f"(c[0]), "+f"(c[1]), "+f"(c[2]), "+f"(c[3])
        : "r"(a[0]), "r"(a[1]), "r"(a[2]), "r"(a[3]), "r"(b[0]), "r"(b[1]));
}
__device__ __forceinline__ uint32_t pkh(__half a, __half b){
    return (uint32_t)__half_as_ushort(a) | ((uint32_t)__half_as_ushort(b) << 16);
}
__device__ __forceinline__ int rpi(int r, int c){
    int ai = r/7, aj = r%7, bi = c/7, bj = c%7;
    return (ai - bi + 6)*13 + (aj - bj + 6);
}

// ---------------- prep: weights (fp16 hi, duplicated), bias fragments ------
__global__ void prep_w(const float* __restrict__ qkv_w,
                       const float* __restrict__ proj_w,
                       const float* __restrict__ rbt)
{
    int idx = blockIdx.x * 256 + threadIdx.x;   // 1024*256 = 262144 = 512*512
    if (idx < 512*512) {
        int j = idx >> 9, c = idx & 511;
        g_B1[idx] = __float2half_rn(qkv_w[j*256 + (c & 255)]);
    }
    if (idx < 256*512) {
        int j = idx >> 9, c = idx & 511;
        g_B2[idx] = __float2half_rn(proj_w[j*256 + (c & 255)]);
    }
    if (idx < HEADS*4*7*32) {
        int lane = idx & 31;
        int nt = (idx >> 5) % 7;
        int mt = (idx >> 5) / 7 % 4;
        int h  = idx / (32*7*4);
        int r0 = mt*16 + (lane>>2), r1 = r0 + 8;
        int c0 = nt*8 + 2*(lane&3), c1 = c0 + 1;
        float4 v;
        v.x = (r0 < 49 && c0 < 49) ? rbt[rpi(r0,c0)*HEADS + h] : -1e30f;
        v.y = (r0 < 49 && c1 < 49) ? rbt[rpi(r0,c1)*HEADS + h] : -1e30f;
        v.z = (r1 < 49 && c0 < 49) ? rbt[rpi(r1,c0)*HEADS + h] : -1e30f;
        v.w = (r1 < 49 && c1 < 49) ? rbt[rpi(r1,c1)*HEADS + h] : -1e30f;
        g_biasF[idx] = v;
    }
}

// ---------------- prep: Q -> A-fragments (scaled, fp16 hi/lo) --------------
__global__ void prep_q(const float* __restrict__ qg)
{
    int idx = blockIdx.x * 256 + threadIdx.x;   // 1024*256 = 262144
    int lane = idx & 31;
    int kind = (idx >> 5) & 3;
    int mt   = (idx >> 7) & 3;
    int h    = (idx >> 9) & 7;
    int img  = idx >> 12;
    int r = mt*16 + (lane>>2);
    int c2 = 2*(lane&3);
    int db = (kind & 1) * 16;
    bool lo = kind >= 2;

    auto qget = [&](int rr, int d) -> __half {
        if (rr >= 49) return __float2half_rn(0.f);
        float v = qg[(((size_t)img*HEADS + h)*NTOK + rr)*HDIM + d] * SCALE;
        __half hv = __float2half_rn(v);
        if (!lo) return hv;
        return __float2half_rn(v - __half2float(hv));
    };
    uint4 o;
    o.x = pkh(qget(r,   db+c2),   qget(r,   db+c2+1));
    o.y = pkh(qget(r+8, db+c2),   qget(r+8, db+c2+1));
    o.z = pkh(qget(r,   db+c2+8), qget(r,   db+c2+9));
    o.w = pkh(qget(r+8, db+c2+8), qget(r+8, db+c2+9));
    g_Qf[idx] = o;
}

// ---------------- convert x -> A1 (fp16 hi|lo), vectorized ----------------
__global__ void conv_x(const float* __restrict__ x)
{
    const float4* x4 = (const float4*)x;
    int stride = gridDim.x * blockDim.x;
    for (int i = blockIdx.x * blockDim.x + threadIdx.x; i < TOKS*64; i += stride) {
        float4 v = __ldg(x4 + i);
        int t = i >> 6, c4 = i & 63;
        __half h0 = __float2half_rn(v.x), h1 = __float2half_rn(v.y);
        __half h2 = __float2half_rn(v.z), h3 = __float2half_rn(v.w);
        __half l0 = __float2half_rn(v.x - __half2float(h0));
        __half l1 = __float2half_rn(v.y - __half2float(h1));
        __half l2 = __float2half_rn(v.z - __half2float(h2));
        __half l3 = __float2half_rn(v.w - __half2float(h3));
        size_t rb = (size_t)t * KD + c4*4;
        *(uint2*)(g_A1 + rb)       = make_uint2(pkh(h0,h1), pkh(h2,h3));
        *(uint2*)(g_A1 + rb + 256) = make_uint2(pkh(l0,l1), pkh(l2,l3));
    }
}

// ---------------- mma.sync fp16 GEMM: C[128,128] per CTA, K=512 ------------
#define GSTAGE 16384
#define GSMEM  (3*2*GSTAGE)    // 96 KB

template<int NOUT>
__global__ void __launch_bounds__(256, 2)
gemm_k(const float* __restrict__ bias, float* __restrict__ extC)
{
    extern __shared__ char sm[];
    const __half* Ag = (NOUT == 512) ? g_A1 : g_A2;
    const __half* Bg = (NOUT == 512) ? g_B1 : g_B2;

    const int tid = threadIdx.x;
    const int n0 = blockIdx.x * 128;
    const int m0 = blockIdx.y * 128;
    const uint32_t sb = smem_u32(sm);

    auto load_stage = [&](int i, int s){
        const char* Abase = (const char*)Ag + ((size_t)m0*KD + (size_t)i*64)*2;
        const char* Bbase = (const char*)Bg + ((size_t)n0*KD + (size_t)i*64)*2;
        uint32_t sa  = sb + s*2*GSTAGE;
        uint32_t sbB = sa + GSTAGE;
        #pragma unroll
        for (int u = 0; u < 4; u++) {
            int idx = tid + u*256;
            int r = idx >> 3, c16 = idx & 7;
            uint32_t dst = (uint32_t)(r*128 + ((c16 ^ (r & 7))*16));
            cp_async16(sa  + dst, Abase + (size_t)r*(KD*2) + c16*16);
            cp_async16(sbB + dst, Bbase + (size_t)r*(KD*2) + c16*16);
        }
        CP_COMMIT();
    };

    const int w = tid >> 5, lane = tid & 31;
    const int wm = w >> 1, wn = w & 1;
    const int aRow = wm*32 + (lane & 15);
    const int aC16 = (lane >> 4);
    const int bRow = wn*64 + (lane & 7) + ((lane >> 4) << 3);
    const int bC16 = (lane >> 3) & 1;
    const int lc2 = 2*(lane & 3);

    float acc[2][8][4];
    #pragma unroll
    for (int mt = 0; mt < 2; mt++)
        #pragma unroll
        for (int nt = 0; nt < 8; nt++)
            #pragma unroll
            for (int q = 0; q < 4; q++) acc[mt][nt][q] = 0.f;

    load_stage(0, 0);
    load_stage(1, 1);
    int s = 0;
    for (int i = 0; i < NITER; i++) {
        if (i < NITER-1) { CP_WAIT1(); } else { CP_WAIT0(); }
        __syncthreads();
        if (i + 2 < NITER) {
            int s2 = s + 2; if (s2 >= 3) s2 -= 3;
            load_stage(i + 2, s2);
        }
        const uint32_t sa  = sb + s*2*GSTAGE;
        const uint32_t sbB = sa + GSTAGE;
        // batch all A fragments for the 4 kk-steps
        uint32_t af[4][2][4];
        #pragma unroll
        for (int kk = 0; kk < 4; kk++)
            #pragma unroll
            for (int mt = 0; mt < 2; mt++) {
                int r = aRow + mt*16, c = kk*2 + aC16;
                ldmx4(af[kk][mt], sa + r*128 + ((c ^ (r & 7))*16));
            }
        #pragma unroll
        for (int kk = 0; kk < 4; kk++) {
            #pragma unroll
            for (int np = 0; np < 4; np++) {
                uint32_t bf[4];
                int r = bRow + np*16, c = kk*2 + bC16;
                ldmx4(bf, sbB + r*128 + ((c ^ (r & 7))*16));
                #pragma unroll
                for (int mt = 0; mt < 2; mt++) {
                    mma16816(acc[mt][np*2+0], af[kk][mt], bf+0);
                    mma16816(acc[mt][np*2+1], af[kk][mt], bf+2);
                }
            }
        }
        if (++s >= 3) s -= 3;
    }

    if (NOUT == 256) {
        #pragma unroll
        for (int nt = 0; nt < 8; nt++) {
            int col = n0 + wn*64 + nt*8 + lc2;
            float bx = __ldg(bias + col), by = __ldg(bias + col + 1);
            #pragma unroll
            for (int mt = 0; mt < 2; mt++) {
                int row = m0 + wm*32 + mt*16 + (lane >> 2);
                float2 v0 = make_float2(acc[mt][nt][0] + bx, acc[mt][nt][1] + by);
                float2 v1 = make_float2(acc[mt][nt][2] + bx, acc[mt][nt][3] + by);
                *(float2*)(extC + (size_t)row*NOUT + col)       = v0;
                *(float2*)(extC + (size_t)(row+8)*NOUT + col)   = v1;
            }
        }
    } else {
        // KV epilogue: K hi-only, V hi+lo — BOTH tok-major 64B rows, same swizzle
        const bool isK = (n0 + wn*64) < 256;
        #pragma unroll
        for (int mt = 0; mt < 2; mt++) {
            int rowb = m0 + wm*32 + mt*16 + (lane >> 2);
            #pragma unroll
            for (int rr = 0; rr < 2; rr++) {
                int r = rowb + rr*8;
                int win = r / 49, tok = r - win*49;
                int key = (tok >> 1) & 3;
                if (isK) {
                    char* base = (char*)g_Ks + (size_t)win*(HEADS*4096) + (size_t)tok*64;
                    #pragma unroll
                    for (int nt = 0; nt < 8; nt++) {
                        int gc = n0 + wn*64 + nt*8 + lc2;
                        float v0 = acc[mt][nt][rr*2]   + __ldg(bias + gc);
                        float v1 = acc[mt][nt][rr*2+1] + __ldg(bias + gc + 1);
                        int head = gc >> 5, d = gc & 31;
                        char* tb = base + head*4096;
                        int chunk = d >> 3, inb = (2*d) & 15;
                        *(uint32_t*)(tb + ((chunk ^ key)*16) + inb)
                            = pkh(__float2half_rn(v0), __float2half_rn(v1));
                    }
                } else {
                    char* base = (char*)g_Vt + (size_t)win*65536 + (size_t)tok*64;
                    #pragma unroll
                    for (int nt = 0; nt < 8; nt++) {
                        int gc = n0 + wn*64 + nt*8 + lc2;
                        float v0 = acc[mt][nt][rr*2]   + __ldg(bias + gc);
                        float v1 = acc[mt][nt][rr*2+1] + __ldg(bias + gc + 1);
                        int c = gc - 256, head = c >> 5, d = c & 31;
                        char* tb = base + head*8192;
                        int chunk = d >> 3, inb = (2*d) & 15;
                        uint32_t off = (uint32_t)(((chunk ^ key)*16) + inb);
                        __half h0 = __float2half_rn(v0), h1 = __float2half_rn(v1);
                        __half l0 = __float2half_rn(v0 - __half2float(h0));
                        __half l1 = __float2half_rn(v1 - __half2float(h1));
                        *(uint32_t*)(tb + off)        = pkh(h0, h1);
                        *(uint32_t*)(tb + 4096 + off) = pkh(l0, l1);
                    }
                }
            }
        }
    }
}

// ---------------- tensor-core attention (fp16) ----------------
#define ASMEM (32768 + 65536)   // K 32KB + V 64KB = 96KB
__global__ void __launch_bounds__(256, 2)
attn_k()
{
    extern __shared__ char sm[];
    const int tid = threadIdx.x, b = blockIdx.x;
    const uint32_t sb = smem_u32(sm);

    {   // stage K (32KB) + V (64KB)
        const char* srcK = (const char*)g_Ks + (size_t)b*32768;
        const char* srcV = (const char*)g_Vt + (size_t)b*65536;
        #pragma unroll
        for (int u = 0; u < 8; u++) {
            int i = tid + u*256;
            cp_async16(sb + i*16, srcK + i*16);
        }
        #pragma unroll
        for (int u = 0; u < 16; u++) {
            int i = tid + u*256;
            cp_async16(sb + 32768 + i*16, srcV + i*16);
        }
        CP_COMMIT(); CP_WAIT0();
    }
    __syncthreads();

    const int h = tid >> 5, lane = tid & 31;
    const int img = b >> 6;
    const uint32_t Kt = sb + h*4096;
    const uint32_t Vt = sb + 32768 + h*8192;   // hi plane; lo at +4096
    const int lr = lane >> 2, lc2 = 2*(lane & 3);
    const int brow = (lane & 7) + ((lane >> 4) << 3);
    const int bch  = (lane >> 3) & 1;
    const int vrow = lane & 15;                // trans-load row within 16
    const int vch  = lane >> 4;                // trans-load n-halfblock

    const uint4*  qf = g_Qf    + ((size_t)(img*HEADS + h)*16)*32 + lane;
    const float4* bf = g_biasF + ((size_t)h*4*7)*32 + lane;

    for (int mt = 0; mt < 4; mt++) {
        uint32_t af[4][4];
        #pragma unroll
        for (int kd = 0; kd < 4; kd++) {
            uint4 v = __ldg(qf + (mt*4 + kd)*32);
            af[kd][0]=v.x; af[kd][1]=v.y; af[kd][2]=v.z; af[kd][3]=v.w;
        }
        float s[8][4];
        #pragma unroll
        for (int nt = 0; nt < 8; nt++)
            #pragma unroll
            for (int j = 0; j < 4; j++) s[nt][j] = 0.f;

        // QK^T: (q_hi + q_lo) x k_hi
        #pragma unroll
        for (int np = 0; np < 4; np++) {
            uint32_t kb[2][4];
            int row = np*16 + brow;
            int key = (row >> 1) & 3;
            #pragma unroll
            for (int ch = 0; ch < 2; ch++) {
                int chunk = ch*2 + bch;
                ldmx4(kb[ch], Kt + row*64 + ((chunk ^ key)*16));
            }
            float* s0 = s[2*np]; float* s1 = s[2*np+1];
            mma16816(s0, af[0], kb[0]+0); mma16816(s1, af[0], kb[0]+2);
            mma16816(s0, af[1], kb[1]+0); mma16816(s1, af[1], kb[1]+2);
            mma16816(s0, af[2], kb[0]+0); mma16816(s1, af[2], kb[0]+2);
            mma16816(s0, af[3], kb[1]+0); mma16816(s1, af[3], kb[1]+2);
        }

        // bias (+mask) and softmax over ntiles 0..6
        float mx0 = -1e30f, mx1 = -1e30f;
        #pragma unroll
        for (int nt = 0; nt < 7; nt++) {
            float4 t = __ldg(bf + (mt*7 + nt)*32);
            s[nt][0] += t.x; s[nt][1] += t.y; s[nt][2] += t.z; s[nt][3] += t.w;
            mx0 = fmaxf(mx0, fmaxf(s[nt][0], s[nt][1]));
            mx1 = fmaxf(mx1, fmaxf(s[nt][2], s[nt][3]));
        }
        mx0 = fmaxf(mx0, __shfl_xor_sync(0xFFFFFFFF, mx0, 1));
        mx0 = fmaxf(mx0, __shfl_xor_sync(0xFFFFFFFF, mx0, 2));
        mx1 = fmaxf(mx1, __shfl_xor_sync(0xFFFFFFFF, mx1, 1));
        mx1 = fmaxf(mx1, __shfl_xor_sync(0xFFFFFFFF, mx1, 2));
        float den0 = 0.f, den1 = 0.f;
        #pragma unroll
        for (int nt = 0; nt < 7; nt++) {
            s[nt][0] = __expf(s[nt][0] - mx0); den0 += s[nt][0];
            s[nt][1] = __expf(s[nt][1] - mx0); den0 += s[nt][1];
            s[nt][2] = __expf(s[nt][2] - mx1); den1 += s[nt][2];
            s[nt][3] = __expf(s[nt][3] - mx1); den1 += s[nt][3];
        }
        den0 += __shfl_xor_sync(0xFFFFFFFF, den0, 1);
        den0 += __shfl_xor_sync(0xFFFFFFFF, den0, 2);
        den1 += __shfl_xor_sync(0xFFFFFFFF, den1, 1);
        den1 += __shfl_xor_sync(0xFFFFFFFF, den1, 2);
        float rinv0 = 1.f / den0, rinv1 = 1.f / den1;

        // P -> A fragments (fp16 hi/lo)
        uint32_t ph[4][4], pl[4][4];
        #pragma unroll
        for (int ks = 0; ks < 4; ks++) {
            #pragma unroll
            for (int half_ = 0; half_ < 2; half_++) {
                int nt = 2*ks + half_;
                if (nt < 7) {
                    #pragma unroll
                    for (int pr = 0; pr < 2; pr++) {
                        float p0 = s[nt][pr*2], p1 = s[nt][pr*2+1];
                        __half h0 = __float2half_rn(p0), h1 = __float2half_rn(p1);
                        __half q0 = __float2half_rn(p0 - __half2float(h0));
                        __half q1 = __float2half_rn(p1 - __half2float(h1));
                        ph[ks][half_*2+pr] = pkh(h0, h1);
                        pl[ks][half_*2+pr] = pkh(q0, q1);
                    }
                } else {
                    ph[ks][half_*2] = 0; ph[ks][half_*2+1] = 0;
                    pl[ks][half_*2] = 0; pl[ks][half_*2+1] = 0;
                }
            }
        }

        // PV: 3-term, V loaded via ldmatrix.trans from tok-major tiles
        float o[4][4];
        #pragma unroll
        for (int nt = 0; nt < 4; nt++)
            #pragma unroll
            for (int j = 0; j < 4; j++) o[nt][j] = 0.f;
        #pragma unroll
        for (int ks = 0; ks < 4; ks++) {
            int row = ks*16 + vrow;
            int key = (row >> 1) & 3;
            #pragma unroll
            for (int nh = 0; nh < 2; nh++) {
                uint32_t vh[4], vl[4];
                int chunk = nh*2 + vch;
                uint32_t addr = Vt + row*64 + ((chunk ^ key)*16);
                ldmx4t(vh, addr);
                ldmx4t(vl, addr + 4096);
                float* o0 = o[2*nh]; float* o1 = o[2*nh+1];
                mma16816(o0, ph[ks], vh+0); mma16816(o1, ph[ks], vh+2);
                mma16816(o0, pl[ks], vh+0); mma16816(o1, pl[ks], vh+2);
                mma16816(o0, ph[ks], vl+0); mma16816(o1, ph[ks], vl+2);
            }
        }

        // store to g_A2 (fp16 hi | lo, [t][512])
        int r0 = mt*16 + lr, r1 = r0 + 8;
        if (r0 < 49) {
            __half* dst = g_A2 + ((size_t)b*NTOK + r0)*KD;
            #pragma unroll
            for (int nt = 0; nt < 4; nt++) {
                int gc = h*HDIM + nt*8 + lc2;
                float v0 = o[nt][0]*rinv0, v1 = o[nt][1]*rinv0;
                __half h0 = __float2half_rn(v0), h1 = __float2half_rn(v1);
                __half l0 = __float2half_rn(v0 - __half2float(h0));
                __half l1 = __float2half_rn(v1 - __half2float(h1));
                *(uint32_t*)(dst + gc)       = pkh(h0, h1);
                *(uint32_t*)(dst + 256 + gc) = pkh(l0, l1);
            }
        }
        if (r1 < 49) {
            __half* dst = g_A2 + ((size_t)b*NTOK + r1)*KD;
            #pragma unroll
            for (int nt = 0; nt < 4; nt++) {
                int gc = h*HDIM + nt*8 + lc2;
                float v0 = o[nt][2]*rinv1, v1 = o[nt][3]*rinv1;
                __half h0 = __float2half_rn(v0), h1 = __float2half_rn(v1);
                __half l0 = __float2half_rn(v0 - __half2float(h0));
                __half l1 = __float2half_rn(v1 - __half2float(h1));
                *(uint32_t*)(dst + gc)       = pkh(h0, h1);
                *(uint32_t*)(dst + 256 + gc) = pkh(l0, l1);
            }
        }
    }
}

// ---------------- launch ----------------
extern "C" void kernel_launch(void* const* d_in, const int* in_sizes, int n_in,
                              void* d_out, int out_size)
{
    const float* x      = (const float*)d_in[0];
    const float* qg     = (const float*)d_in[1];
    const float* qkv_w  = (const float*)d_in[2];
    const float* qkv_b  = (const float*)d_in[3];
    const float* proj_w = (const float*)d_in[4];
    const float* proj_b = (const float*)d_in[5];
    const float* rbt    = (const float*)d_in[6];
    float* out = (float*)d_out;
    (void)in_sizes; (void)n_in; (void)out_size;

    cudaFuncSetAttribute(gemm_k<512>, cudaFuncAttributeMaxDynamicSharedMemorySize, GSMEM);
    cudaFuncSetAttribute(gemm_k<256>, cudaFuncAttributeMaxDynamicSharedMemorySize, GSMEM);
    cudaFuncSetAttribute(attn_k,      cudaFuncAttributeMaxDynamicSharedMemorySize, ASMEM);

    prep_w<<<1024, 256>>>(qkv_w, proj_w, rbt);
    prep_q<<<1024, 256>>>(qg);
    conv_x<<<4096, 256>>>(x);
    {
        dim3 g1(4, TOKS/128);
        gemm_k<512><<<g1, 256, GSMEM>>>(qkv_b, nullptr);
    }
    attn_k<<<BWIN, 256, ASMEM>>>();
    {
        dim3 g2(2, TOKS/128);
        gemm_k<256><<<g2, 256, GSMEM>>>(proj_b, out);
    }
}

// round 9
// speedup vs baseline: 2.9808x; 1.3984x over previous
#include <cuda_runtime.h>
#include <cuda_fp16.h>
#include <cstdint>
#include <math.h>

#define NTOK   49
#define CDIM   256
#define HEADS  8
#define HDIM   32
#define BWIN   4096
#define TOKS   (BWIN*NTOK)          // 200704 = 1568 * 128
#define KD     256                  // plain fp16, no split
#define NITER  4                    // K/64
#define SCALE  0.17677669529663688f

// ---------------- scratch (device globals; no allocs) ----------------
__device__ __half g_A1[(size_t)TOKS*KD];   // fp16(x)   [t][256]
__device__ __half g_A2[(size_t)TOKS*KD];   // attn-out  [t][256]
__device__ __half g_B1[512*KD];            // fp16(qkv_w)  [n][256]
__device__ __half g_B2[256*KD];            // fp16(proj_w) [n][256]
// K tiles: [win][head] 64 tok-rows x 64B (32 fp16), swizzle key (tok>>1)&3. pads stay 0.
__device__ unsigned char g_Ks[(size_t)BWIN*HEADS*4096];
// V tiles: [win][head] { hi: 64 tok-rows x 64B ; lo same } = 8KB, tok-major. pads stay 0.
__device__ unsigned char g_Vt[(size_t)BWIN*HEADS*8192];
// Q fragments: [img][head][mtile 4][kind 4][lane 32] uint4
__device__ uint4  g_Qf[64*HEADS*4*4*32];
// bias in C-fragment layout, mask folded: [head][mtile 4][ntile 7][lane 32] float4
__device__ float4 g_biasF[HEADS*4*7*32];

// ---------------- helpers ----------------
__device__ __forceinline__ uint32_t smem_u32(const void* p){
    uint32_t a;
    asm("{ .reg .u64 t; cvta.to.shared.u64 t, %1; cvt.u32.u64 %0, t; }" : "=r"(a) : "l"(p));
    return a;
}
__device__ __forceinline__ void cp_async16(uint32_t dst, const void* src){
    asm volatile("cp.async.cg.shared.global [%0], [%1], 16;" :: "r"(dst), "l"(src));
}
#define CP_COMMIT() asm volatile("cp.async.commit_group;")
#define CP_WAIT1()  asm volatile("cp.async.wait_group 1;")
#define CP_WAIT0()  asm volatile("cp.async.wait_group 0;")

__device__ __forceinline__ void ldmx4(uint32_t* r, uint32_t addr){
    asm volatile("ldmatrix.sync.aligned.m8n8.x4.shared.b16 {%0,%1,%2,%3}, [%4];"
        : "=r"(r[0]), "=r"(r[1]), "=r"(r[2]), "=r"(r[3]) : "r"(addr));
}
__device__ __forceinline__ void ldmx4t(uint32_t* r, uint32_t addr){
    asm volatile("ldmatrix.sync.aligned.m8n8.x4.trans.shared.b16 {%0,%1,%2,%3}, [%4];"
        : "=r"(r[0]), "=r"(r[1]), "=r"(r[2]), "=r"(r[3]) : "r"(addr));
}
__device__ __forceinline__ void mma16816(float* c, const uint32_t* a, const uint32_t* b){
    asm volatile("mma.sync.aligned.m16n8k16.row.col.f32.f16.f16.f32 "
        "{%0,%1,%2,%3}, {%4,%5,%6,%7}, {%8,%9}, {%0,%1,%2,%3};"
        : "+f"(c[0]), "+f"(c[1]), "+f"(c[2]), "+f"(c[3])
        : "r"(a[0]), "r"(a[1]), "r"(a[2]), "r"(a[3]), "r"(b[0]), "r"(b[1]));
}
__device__ __forceinline__ uint32_t pkh(__half a, __half b){
    return (uint32_t)__half_as_ushort(a) | ((uint32_t)__half_as_ushort(b) << 16);
}
__device__ __forceinline__ int rpi(int r, int c){
    int ai = r/7, aj = r%7, bi = c/7, bj = c%7;
    return (ai - bi + 6)*13 + (aj - bj + 6);
}

// ---------------- prep: weights fp16, bias fragments ------
__global__ void prep_w(const float* __restrict__ qkv_w,
                       const float* __restrict__ proj_w,
                       const float* __restrict__ rbt)
{
    int idx = blockIdx.x * 256 + threadIdx.x;   // 512*256 = 131072 = 512*256
    if (idx < 512*256) {
        g_B1[idx] = __float2half_rn(qkv_w[idx]);
    }
    if (idx < 256*256) {
        g_B2[idx] = __float2half_rn(proj_w[idx]);
    }
    if (idx < HEADS*4*7*32) {
        int lane = idx & 31;
        int nt = (idx >> 5) % 7;
        int mt = (idx >> 5) / 7 % 4;
        int h  = idx / (32*7*4);
        int r0 = mt*16 + (lane>>2), r1 = r0 + 8;
        int c0 = nt*8 + 2*(lane&3), c1 = c0 + 1;
        float4 v;
        v.x = (r0 < 49 && c0 < 49) ? rbt[rpi(r0,c0)*HEADS + h] : -1e30f;
        v.y = (r0 < 49 && c1 < 49) ? rbt[rpi(r0,c1)*HEADS + h] : -1e30f;
        v.z = (r1 < 49 && c0 < 49) ? rbt[rpi(r1,c0)*HEADS + h] : -1e30f;
        v.w = (r1 < 49 && c1 < 49) ? rbt[rpi(r1,c1)*HEADS + h] : -1e30f;
        g_biasF[idx] = v;
    }
}

// ---------------- prep: Q -> A-fragments (scaled, fp16 hi/lo) --------------
__global__ void prep_q(const float* __restrict__ qg)
{
    int idx = blockIdx.x * 256 + threadIdx.x;   // 1024*256 = 262144
    int lane = idx & 31;
    int kind = (idx >> 5) & 3;
    int mt   = (idx >> 7) & 3;
    int h    = (idx >> 9) & 7;
    int img  = idx >> 12;
    int r = mt*16 + (lane>>2);
    int c2 = 2*(lane&3);
    int db = (kind & 1) * 16;
    bool lo = kind >= 2;

    auto qget = [&](int rr, int d) -> __half {
        if (rr >= 49) return __float2half_rn(0.f);
        float v = qg[(((size_t)img*HEADS + h)*NTOK + rr)*HDIM + d] * SCALE;
        __half hv = __float2half_rn(v);
        if (!lo) return hv;
        return __float2half_rn(v - __half2float(hv));
    };
    uint4 o;
    o.x = pkh(qget(r,   db+c2),   qget(r,   db+c2+1));
    o.y = pkh(qget(r+8, db+c2),   qget(r+8, db+c2+1));
    o.z = pkh(qget(r,   db+c2+8), qget(r,   db+c2+9));
    o.w = pkh(qget(r+8, db+c2+8), qget(r+8, db+c2+9));
    g_Qf[idx] = o;
}

// ---------------- convert x -> A1 (fp16), vectorized ----------------
__global__ void conv_x(const float* __restrict__ x)
{
    const float4* x4 = (const float4*)x;
    int stride = gridDim.x * blockDim.x;
    for (int i = blockIdx.x * blockDim.x + threadIdx.x; i < TOKS*64; i += stride) {
        float4 v = __ldg(x4 + i);
        __half h0 = __float2half_rn(v.x), h1 = __float2half_rn(v.y);
        __half h2 = __float2half_rn(v.z), h3 = __float2half_rn(v.w);
        *(uint2*)(g_A1 + (size_t)i*4) = make_uint2(pkh(h0,h1), pkh(h2,h3));
    }
}

// ---------------- mma.sync fp16 GEMM: C[128,128] per CTA, K=256 ------------
#define GSTAGE 16384
#define GSMEM  (3*2*GSTAGE)    // 96 KB

template<int NOUT>
__global__ void __launch_bounds__(256, 2)
gemm_k(const float* __restrict__ bias, float* __restrict__ extC)
{
    extern __shared__ char sm[];
    const __half* Ag = (NOUT == 512) ? g_A1 : g_A2;
    const __half* Bg = (NOUT == 512) ? g_B1 : g_B2;

    const int tid = threadIdx.x;
    const int n0 = blockIdx.x * 128;
    const int m0 = blockIdx.y * 128;
    const uint32_t sb = smem_u32(sm);

    auto load_stage = [&](int i, int s){
        const char* Abase = (const char*)Ag + ((size_t)m0*KD + (size_t)i*64)*2;
        const char* Bbase = (const char*)Bg + ((size_t)n0*KD + (size_t)i*64)*2;
        uint32_t sa  = sb + s*2*GSTAGE;
        uint32_t sbB = sa + GSTAGE;
        #pragma unroll
        for (int u = 0; u < 4; u++) {
            int idx = tid + u*256;
            int r = idx >> 3, c16 = idx & 7;
            uint32_t dst = (uint32_t)(r*128 + ((c16 ^ (r & 7))*16));
            cp_async16(sa  + dst, Abase + (size_t)r*(KD*2) + c16*16);
            cp_async16(sbB + dst, Bbase + (size_t)r*(KD*2) + c16*16);
        }
        CP_COMMIT();
    };

    const int w = tid >> 5, lane = tid & 31;
    const int wm = w >> 1, wn = w & 1;
    const int aRow = wm*32 + (lane & 15);
    const int aC16 = (lane >> 4);
    const int bRow = wn*64 + (lane & 7) + ((lane >> 4) << 3);
    const int bC16 = (lane >> 3) & 1;
    const int lc2 = 2*(lane & 3);

    float acc[2][8][4];
    #pragma unroll
    for (int mt = 0; mt < 2; mt++)
        #pragma unroll
        for (int nt = 0; nt < 8; nt++)
            #pragma unroll
            for (int q = 0; q < 4; q++) acc[mt][nt][q] = 0.f;

    load_stage(0, 0);
    load_stage(1, 1);
    int s = 0;
    for (int i = 0; i < NITER; i++) {
        if (i < NITER-1) { CP_WAIT1(); } else { CP_WAIT0(); }
        __syncthreads();
        if (i + 2 < NITER) {
            int s2 = s + 2; if (s2 >= 3) s2 -= 3;
            load_stage(i + 2, s2);
        }
        const uint32_t sa  = sb + s*2*GSTAGE;
        const uint32_t sbB = sa + GSTAGE;
        uint32_t af[4][2][4];
        #pragma unroll
        for (int kk = 0; kk < 4; kk++)
            #pragma unroll
            for (int mt = 0; mt < 2; mt++) {
                int r = aRow + mt*16, c = kk*2 + aC16;
                ldmx4(af[kk][mt], sa + r*128 + ((c ^ (r & 7))*16));
            }
        #pragma unroll
        for (int kk = 0; kk < 4; kk++) {
            #pragma unroll
            for (int np = 0; np < 4; np++) {
                uint32_t bf[4];
                int r = bRow + np*16, c = kk*2 + bC16;
                ldmx4(bf, sbB + r*128 + ((c ^ (r & 7))*16));
                #pragma unroll
                for (int mt = 0; mt < 2; mt++) {
                    mma16816(acc[mt][np*2+0], af[kk][mt], bf+0);
                    mma16816(acc[mt][np*2+1], af[kk][mt], bf+2);
                }
            }
        }
        if (++s >= 3) s -= 3;
    }

    if (NOUT == 256) {
        #pragma unroll
        for (int nt = 0; nt < 8; nt++) {
            int col = n0 + wn*64 + nt*8 + lc2;
            float bx = __ldg(bias + col), by = __ldg(bias + col + 1);
            #pragma unroll
            for (int mt = 0; mt < 2; mt++) {
                int row = m0 + wm*32 + mt*16 + (lane >> 2);
                float2 v0 = make_float2(acc[mt][nt][0] + bx, acc[mt][nt][1] + by);
                float2 v1 = make_float2(acc[mt][nt][2] + bx, acc[mt][nt][3] + by);
                *(float2*)(extC + (size_t)row*NOUT + col)       = v0;
                *(float2*)(extC + (size_t)(row+8)*NOUT + col)   = v1;
            }
        }
    } else {
        // KV epilogue: K hi-only, V hi+lo — BOTH tok-major 64B rows, same swizzle
        const bool isK = (n0 + wn*64) < 256;
        #pragma unroll
        for (int mt = 0; mt < 2; mt++) {
            int rowb = m0 + wm*32 + mt*16 + (lane >> 2);
            #pragma unroll
            for (int rr = 0; rr < 2; rr++) {
                int r = rowb + rr*8;
                int win = r / 49, tok = r - win*49;
                int key = (tok >> 1) & 3;
                if (isK) {
                    char* base = (char*)g_Ks + (size_t)win*(HEADS*4096) + (size_t)tok*64;
                    #pragma unroll
                    for (int nt = 0; nt < 8; nt++) {
                        int gc = n0 + wn*64 + nt*8 + lc2;
                        float v0 = acc[mt][nt][rr*2]   + __ldg(bias + gc);
                        float v1 = acc[mt][nt][rr*2+1] + __ldg(bias + gc + 1);
                        int head = gc >> 5, d = gc & 31;
                        char* tb = base + head*4096;
                        int chunk = d >> 3, inb = (2*d) & 15;
                        *(uint32_t*)(tb + ((chunk ^ key)*16) + inb)
                            = pkh(__float2half_rn(v0), __float2half_rn(v1));
                    }
                } else {
                    char* base = (char*)g_Vt + (size_t)win*65536 + (size_t)tok*64;
                    #pragma unroll
                    for (int nt = 0; nt < 8; nt++) {
                        int gc = n0 + wn*64 + nt*8 + lc2;
                        float v0 = acc[mt][nt][rr*2]   + __ldg(bias + gc);
                        float v1 = acc[mt][nt][rr*2+1] + __ldg(bias + gc + 1);
                        int c = gc - 256, head = c >> 5, d = c & 31;
                        char* tb = base + head*8192;
                        int chunk = d >> 3, inb = (2*d) & 15;
                        uint32_t off = (uint32_t)(((chunk ^ key)*16) + inb);
                        __half h0 = __float2half_rn(v0), h1 = __float2half_rn(v1);
                        __half l0 = __float2half_rn(v0 - __half2float(h0));
                        __half l1 = __float2half_rn(v1 - __half2float(h1));
                        *(uint32_t*)(tb + off)        = pkh(h0, h1);
                        *(uint32_t*)(tb + 4096 + off) = pkh(l0, l1);
                    }
                }
            }
        }
    }
}

// ---------------- tensor-core attention (fp16) ----------------
#define ASMEM (32768 + 65536)   // K 32KB + V 64KB = 96KB
__global__ void __launch_bounds__(256, 2)
attn_k()
{
    extern __shared__ char sm[];
    const int tid = threadIdx.x, b = blockIdx.x;
    const uint32_t sb = smem_u32(sm);

    {   // stage K (32KB) + V (64KB)
        const char* srcK = (const char*)g_Ks + (size_t)b*32768;
        const char* srcV = (const char*)g_Vt + (size_t)b*65536;
        #pragma unroll
        for (int u = 0; u < 8; u++) {
            int i = tid + u*256;
            cp_async16(sb + i*16, srcK + i*16);
        }
        #pragma unroll
        for (int u = 0; u < 16; u++) {
            int i = tid + u*256;
            cp_async16(sb + 32768 + i*16, srcV + i*16);
        }
        CP_COMMIT(); CP_WAIT0();
    }
    __syncthreads();

    const int h = tid >> 5, lane = tid & 31;
    const int img = b >> 6;
    const uint32_t Kt = sb + h*4096;
    const uint32_t Vt = sb + 32768 + h*8192;   // hi plane; lo at +4096
    const int lr = lane >> 2, lc2 = 2*(lane & 3);
    const int brow = (lane & 7) + ((lane >> 4) << 3);
    const int bch  = (lane >> 3) & 1;
    const int vrow = lane & 15;
    const int vch  = lane >> 4;

    const uint4*  qf = g_Qf    + ((size_t)(img*HEADS + h)*16)*32 + lane;
    const float4* bf = g_biasF + ((size_t)h*4*7)*32 + lane;

    for (int mt = 0; mt < 4; mt++) {
        uint32_t af[4][4];
        #pragma unroll
        for (int kd = 0; kd < 4; kd++) {
            uint4 v = __ldg(qf + (mt*4 + kd)*32);
            af[kd][0]=v.x; af[kd][1]=v.y; af[kd][2]=v.z; af[kd][3]=v.w;
        }
        float s[8][4];
        #pragma unroll
        for (int nt = 0; nt < 8; nt++)
            #pragma unroll
            for (int j = 0; j < 4; j++) s[nt][j] = 0.f;

        // QK^T: (q_hi + q_lo) x k_hi
        #pragma unroll
        for (int np = 0; np < 4; np++) {
            uint32_t kb[2][4];
            int row = np*16 + brow;
            int key = (row >> 1) & 3;
            #pragma unroll
            for (int ch = 0; ch < 2; ch++) {
                int chunk = ch*2 + bch;
                ldmx4(kb[ch], Kt + row*64 + ((chunk ^ key)*16));
            }
            float* s0 = s[2*np]; float* s1 = s[2*np+1];
            mma16816(s0, af[0], kb[0]+0); mma16816(s1, af[0], kb[0]+2);
            mma16816(s0, af[1], kb[1]+0); mma16816(s1, af[1], kb[1]+2);
            mma16816(s0, af[2], kb[0]+0); mma16816(s1, af[2], kb[0]+2);
            mma16816(s0, af[3], kb[1]+0); mma16816(s1, af[3], kb[1]+2);
        }

        // bias (+mask) and softmax over ntiles 0..6
        float mx0 = -1e30f, mx1 = -1e30f;
        #pragma unroll
        for (int nt = 0; nt < 7; nt++) {
            float4 t = __ldg(bf + (mt*7 + nt)*32);
            s[nt][0] += t.x; s[nt][1] += t.y; s[nt][2] += t.z; s[nt][3] += t.w;
            mx0 = fmaxf(mx0, fmaxf(s[nt][0], s[nt][1]));
            mx1 = fmaxf(mx1, fmaxf(s[nt][2], s[nt][3]));
        }
        mx0 = fmaxf(mx0, __shfl_xor_sync(0xFFFFFFFF, mx0, 1));
        mx0 = fmaxf(mx0, __shfl_xor_sync(0xFFFFFFFF, mx0, 2));
        mx1 = fmaxf(mx1, __shfl_xor_sync(0xFFFFFFFF, mx1, 1));
        mx1 = fmaxf(mx1, __shfl_xor_sync(0xFFFFFFFF, mx1, 2));
        float den0 = 0.f, den1 = 0.f;
        #pragma unroll
        for (int nt = 0; nt < 7; nt++) {
            s[nt][0] = __expf(s[nt][0] - mx0); den0 += s[nt][0];
            s[nt][1] = __expf(s[nt][1] - mx0); den0 += s[nt][1];
            s[nt][2] = __expf(s[nt][2] - mx1); den1 += s[nt][2];
            s[nt][3] = __expf(s[nt][3] - mx1); den1 += s[nt][3];
        }
        den0 += __shfl_xor_sync(0xFFFFFFFF, den0, 1);
        den0 += __shfl_xor_sync(0xFFFFFFFF, den0, 2);
        den1 += __shfl_xor_sync(0xFFFFFFFF, den1, 1);
        den1 += __shfl_xor_sync(0xFFFFFFFF, den1, 2);
        float rinv0 = 1.f / den0, rinv1 = 1.f / den1;

        // P -> A fragments (fp16 hi/lo)
        uint32_t ph[4][4], pl[4][4];
        #pragma unroll
        for (int ks = 0; ks < 4; ks++) {
            #pragma unroll
            for (int half_ = 0; half_ < 2; half_++) {
                int nt = 2*ks + half_;
                if (nt < 7) {
                    #pragma unroll
                    for (int pr = 0; pr < 2; pr++) {
                        float p0 = s[nt][pr*2], p1 = s[nt][pr*2+1];
                        __half h0 = __float2half_rn(p0), h1 = __float2half_rn(p1);
                        __half q0 = __float2half_rn(p0 - __half2float(h0));
                        __half q1 = __float2half_rn(p1 - __half2float(h1));
                        ph[ks][half_*2+pr] = pkh(h0, h1);
                        pl[ks][half_*2+pr] = pkh(q0, q1);
                    }
                } else {
                    ph[ks][half_*2] = 0; ph[ks][half_*2+1] = 0;
                    pl[ks][half_*2] = 0; pl[ks][half_*2+1] = 0;
                }
            }
        }

        // PV: 3-term, V loaded via ldmatrix.trans from tok-major tiles
        float o[4][4];
        #pragma unroll
        for (int nt = 0; nt < 4; nt++)
            #pragma unroll
            for (int j = 0; j < 4; j++) o[nt][j] = 0.f;
        #pragma unroll
        for (int ks = 0; ks < 4; ks++) {
            int row = ks*16 + vrow;
            int key = (row >> 1) & 3;
            #pragma unroll
            for (int nh = 0; nh < 2; nh++) {
                uint32_t vh[4], vl[4];
                int chunk = nh*2 + vch;
                uint32_t addr = Vt + row*64 + ((chunk ^ key)*16);
                ldmx4t(vh, addr);
                ldmx4t(vl, addr + 4096);
                float* o0 = o[2*nh]; float* o1 = o[2*nh+1];
                mma16816(o0, ph[ks], vh+0); mma16816(o1, ph[ks], vh+2);
                mma16816(o0, pl[ks], vh+0); mma16816(o1, pl[ks], vh+2);
                mma16816(o0, ph[ks], vl+0); mma16816(o1, ph[ks], vl+2);
            }
        }

        // store to g_A2 (fp16, [t][256])
        int r0 = mt*16 + lr, r1 = r0 + 8;
        if (r0 < 49) {
            __half* dst = g_A2 + ((size_t)b*NTOK + r0)*KD;
            #pragma unroll
            for (int nt = 0; nt < 4; nt++) {
                int gc = h*HDIM + nt*8 + lc2;
                *(uint32_t*)(dst + gc) = pkh(__float2half_rn(o[nt][0]*rinv0),
                                             __float2half_rn(o[nt][1]*rinv0));
            }
        }
        if (r1 < 49) {
            __half* dst = g_A2 + ((size_t)b*NTOK + r1)*KD;
            #pragma unroll
            for (int nt = 0; nt < 4; nt++) {
                int gc = h*HDIM + nt*8 + lc2;
                *(uint32_t*)(dst + gc) = pkh(__float2half_rn(o[nt][2]*rinv1),
                                             __float2half_rn(o[nt][3]*rinv1));
            }
        }
    }
}

// ---------------- launch ----------------
extern "C" void kernel_launch(void* const* d_in, const int* in_sizes, int n_in,
                              void* d_out, int out_size)
{
    const float* x      = (const float*)d_in[0];
    const float* qg     = (const float*)d_in[1];
    const float* qkv_w  = (const float*)d_in[2];
    const float* qkv_b  = (const float*)d_in[3];
    const float* proj_w = (const float*)d_in[4];
    const float* proj_b = (const float*)d_in[5];
    const float* rbt    = (const float*)d_in[6];
    float* out = (float*)d_out;
    (void)in_sizes; (void)n_in; (void)out_size;

    cudaFuncSetAttribute(gemm_k<512>, cudaFuncAttributeMaxDynamicSharedMemorySize, GSMEM);
    cudaFuncSetAttribute(gemm_k<256>, cudaFuncAttributeMaxDynamicSharedMemorySize, GSMEM);
    cudaFuncSetAttribute(attn_k,      cudaFuncAttributeMaxDynamicSharedMemorySize, ASMEM);

    prep_w<<<512, 256>>>(qkv_w, proj_w, rbt);
    prep_q<<<1024, 256>>>(qg);
    conv_x<<<4096, 256>>>(x);
    {
        dim3 g1(4, TOKS/128);
        gemm_k<512><<<g1, 256, GSMEM>>>(qkv_b, nullptr);
    }
    attn_k<<<BWIN, 256, ASMEM>>>();
    {
        dim3 g2(2, TOKS/128);
        gemm_k<256><<<g2, 256, GSMEM>>>(proj_b, out);
    }
}

// round 10
// speedup vs baseline: 3.4144x; 1.1455x over previous
#include <cuda_runtime.h>
#include <cuda_fp16.h>
#include <cstdint>
#include <math.h>

#define NTOK   49
#define CDIM   256
#define HEADS  8
#define HDIM   32
#define BWIN   4096
#define TOKS   (BWIN*NTOK)          // 200704 = 1568 * 128
#define KD     256                  // plain fp16
#define NITER  4                    // K/64
#define SCALE  0.17677669529663688f

// ---------------- scratch (device globals; no allocs) ----------------
__device__ __half g_A1[(size_t)TOKS*KD];   // fp16(x)   [t][256]
__device__ __half g_A2[(size_t)TOKS*KD];   // attn-out  [t][256]
__device__ __half g_B1[512*KD];            // fp16(qkv_w)
__device__ __half g_B2[256*KD];            // fp16(proj_w)
// K and V tiles: [win][head] 64 tok-rows x 64B (32 fp16), swizzle key (tok>>1)&3. pads stay 0.
__device__ unsigned char g_Ks[(size_t)BWIN*HEADS*4096];
__device__ unsigned char g_Vt[(size_t)BWIN*HEADS*4096];
// Q fragments: [img][head][mtile 4][kind 2][lane 32] uint4  (hi d0-15, hi d16-31)
__device__ uint4  g_Qf[64*HEADS*4*2*32];
// bias in C-fragment layout, mask folded: [head][mtile 4][ntile 7][lane 32] float4
__device__ float4 g_biasF[HEADS*4*7*32];

// ---------------- helpers ----------------
__device__ __forceinline__ uint32_t smem_u32(const void* p){
    uint32_t a;
    asm("{ .reg .u64 t; cvta.to.shared.u64 t, %1; cvt.u32.u64 %0, t; }" : "=r"(a) : "l"(p));
    return a;
}
__device__ __forceinline__ void cp_async16(uint32_t dst, const void* src){
    asm volatile("cp.async.cg.shared.global [%0], [%1], 16;" :: "r"(dst), "l"(src));
}
#define CP_COMMIT() asm volatile("cp.async.commit_group;")
#define CP_WAIT1()  asm volatile("cp.async.wait_group 1;")
#define CP_WAIT0()  asm volatile("cp.async.wait_group 0;")

__device__ __forceinline__ void ldmx4(uint32_t* r, uint32_t addr){
    asm volatile("ldmatrix.sync.aligned.m8n8.x4.shared.b16 {%0,%1,%2,%3}, [%4];"
        : "=r"(r[0]), "=r"(r[1]), "=r"(r[2]), "=r"(r[3]) : "r"(addr));
}
__device__ __forceinline__ void ldmx4t(uint32_t* r, uint32_t addr){
    asm volatile("ldmatrix.sync.aligned.m8n8.x4.trans.shared.b16 {%0,%1,%2,%3}, [%4];"
        : "=r"(r[0]), "=r"(r[1]), "=r"(r[2]), "=r"(r[3]) : "r"(addr));
}
__device__ __forceinline__ void mma16816(float* c, const uint32_t* a, const uint32_t* b){
    asm volatile("mma.sync.aligned.m16n8k16.row.col.f32.f16.f16.f32 "
        "{%0,%1,%2,%3}, {%4,%5,%6,%7}, {%8,%9}, {%0,%1,%2,%3};"
        : "+f"(c[0]), "+f"(c[1]), "+f"(c[2]), "+f"(c[3])
        : "r"(a[0]), "r"(a[1]), "r"(a[2]), "r"(a[3]), "r"(b[0]), "r"(b[1]));
}
__device__ __forceinline__ uint32_t pkh(__half a, __half b){
    return (uint32_t)__half_as_ushort(a) | ((uint32_t)__half_as_ushort(b) << 16);
}
__device__ __forceinline__ int rpi(int r, int c){
    int ai = r/7, aj = r%7, bi = c/7, bj = c%7;
    return (ai - bi + 6)*13 + (aj - bj + 6);
}

// ---------------- prep: weights fp16, bias fragments, Q fragments ----------
__global__ void prep_all(const float* __restrict__ qkv_w,
                         const float* __restrict__ proj_w,
                         const float* __restrict__ rbt,
                         const float* __restrict__ qg)
{
    int idx = blockIdx.x * 256 + threadIdx.x;   // 512*256 = 131072
    if (idx < 512*256) g_B1[idx] = __float2half_rn(qkv_w[idx]);
    if (idx < 256*256) g_B2[idx] = __float2half_rn(proj_w[idx]);
    if (idx < HEADS*4*7*32) {
        int lane = idx & 31;
        int nt = (idx >> 5) % 7;
        int mt = (idx >> 5) / 7 % 4;
        int h  = idx / (32*7*4);
        int r0 = mt*16 + (lane>>2), r1 = r0 + 8;
        int c0 = nt*8 + 2*(lane&3), c1 = c0 + 1;
        float4 v;
        v.x = (r0 < 49 && c0 < 49) ? rbt[rpi(r0,c0)*HEADS + h] : -1e30f;
        v.y = (r0 < 49 && c1 < 49) ? rbt[rpi(r0,c1)*HEADS + h] : -1e30f;
        v.z = (r1 < 49 && c0 < 49) ? rbt[rpi(r1,c0)*HEADS + h] : -1e30f;
        v.w = (r1 < 49 && c1 < 49) ? rbt[rpi(r1,c1)*HEADS + h] : -1e30f;
        g_biasF[idx] = v;
    }
    {   // Q fragments: idx covers 64*8*4*2*32 = 131072
        int lane = idx & 31;
        int kind = (idx >> 5) & 1;
        int mt   = (idx >> 6) & 3;
        int h    = (idx >> 8) & 7;
        int img  = idx >> 11;
        int r = mt*16 + (lane>>2);
        int c2 = 2*(lane&3);
        int db = kind * 16;
        auto qget = [&](int rr, int d) -> __half {
            if (rr >= 49) return __float2half_rn(0.f);
            return __float2half_rn(qg[(((size_t)img*HEADS + h)*NTOK + rr)*HDIM + d] * SCALE);
        };
        uint4 o;
        o.x = pkh(qget(r,   db+c2),   qget(r,   db+c2+1));
        o.y = pkh(qget(r+8, db+c2),   qget(r+8, db+c2+1));
        o.z = pkh(qget(r,   db+c2+8), qget(r,   db+c2+9));
        o.w = pkh(qget(r+8, db+c2+8), qget(r+8, db+c2+9));
        g_Qf[idx] = o;
    }
}

// ---------------- convert x -> A1 (fp16), vectorized ----------------
__global__ void conv_x(const float* __restrict__ x)
{
    const float4* x4 = (const float4*)x;
    int stride = gridDim.x * blockDim.x;
    for (int i = blockIdx.x * blockDim.x + threadIdx.x; i < TOKS*64; i += stride) {
        float4 v = __ldg(x4 + i);
        __half h0 = __float2half_rn(v.x), h1 = __float2half_rn(v.y);
        __half h2 = __float2half_rn(v.z), h3 = __float2half_rn(v.w);
        *(uint2*)(g_A1 + (size_t)i*4) = make_uint2(pkh(h0,h1), pkh(h2,h3));
    }
}

// ---------------- mma.sync fp16 GEMM: C[128,128] per CTA, K=256 ------------
#define GSTAGE 16384
#define GSMEM  (3*2*GSTAGE)    // 96 KB

template<int NOUT>
__global__ void __launch_bounds__(256, 2)
gemm_k(const float* __restrict__ bias, float* __restrict__ extC)
{
    extern __shared__ char sm[];
    const __half* Ag = (NOUT == 512) ? g_A1 : g_A2;
    const __half* Bg = (NOUT == 512) ? g_B1 : g_B2;

    const int tid = threadIdx.x;
    const int n0 = blockIdx.x * 128;
    const int m0 = blockIdx.y * 128;
    const uint32_t sb = smem_u32(sm);

    auto load_stage = [&](int i, int s){
        const char* Abase = (const char*)Ag + ((size_t)m0*KD + (size_t)i*64)*2;
        const char* Bbase = (const char*)Bg + ((size_t)n0*KD + (size_t)i*64)*2;
        uint32_t sa  = sb + s*2*GSTAGE;
        uint32_t sbB = sa + GSTAGE;
        #pragma unroll
        for (int u = 0; u < 4; u++) {
            int idx = tid + u*256;
            int r = idx >> 3, c16 = idx & 7;
            uint32_t dst = (uint32_t)(r*128 + ((c16 ^ (r & 7))*16));
            cp_async16(sa  + dst, Abase + (size_t)r*(KD*2) + c16*16);
            cp_async16(sbB + dst, Bbase + (size_t)r*(KD*2) + c16*16);
        }
        CP_COMMIT();
    };

    const int w = tid >> 5, lane = tid & 31;
    const int wm = w >> 1, wn = w & 1;
    const int aRow = wm*32 + (lane & 15);
    const int aC16 = (lane >> 4);
    const int bRow = wn*64 + (lane & 7) + ((lane >> 4) << 3);
    const int bC16 = (lane >> 3) & 1;
    const int lc2 = 2*(lane & 3);

    float acc[2][8][4];
    #pragma unroll
    for (int mt = 0; mt < 2; mt++)
        #pragma unroll
        for (int nt = 0; nt < 8; nt++)
            #pragma unroll
            for (int q = 0; q < 4; q++) acc[mt][nt][q] = 0.f;

    load_stage(0, 0);
    load_stage(1, 1);
    int s = 0;
    for (int i = 0; i < NITER; i++) {
        if (i < NITER-1) { CP_WAIT1(); } else { CP_WAIT0(); }
        __syncthreads();
        if (i + 2 < NITER) {
            int s2 = s + 2; if (s2 >= 3) s2 -= 3;
            load_stage(i + 2, s2);
        }
        const uint32_t sa  = sb + s*2*GSTAGE;
        const uint32_t sbB = sa + GSTAGE;
        uint32_t af[4][2][4];
        #pragma unroll
        for (int kk = 0; kk < 4; kk++)
            #pragma unroll
            for (int mt = 0; mt < 2; mt++) {
                int r = aRow + mt*16, c = kk*2 + aC16;
                ldmx4(af[kk][mt], sa + r*128 + ((c ^ (r & 7))*16));
            }
        #pragma unroll
        for (int kk = 0; kk < 4; kk++) {
            #pragma unroll
            for (int np = 0; np < 4; np++) {
                uint32_t bf[4];
                int r = bRow + np*16, c = kk*2 + bC16;
                ldmx4(bf, sbB + r*128 + ((c ^ (r & 7))*16));
                #pragma unroll
                for (int mt = 0; mt < 2; mt++) {
                    mma16816(acc[mt][np*2+0], af[kk][mt], bf+0);
                    mma16816(acc[mt][np*2+1], af[kk][mt], bf+2);
                }
            }
        }
        if (++s >= 3) s -= 3;
    }

    if (NOUT == 256) {
        #pragma unroll
        for (int nt = 0; nt < 8; nt++) {
            int col = n0 + wn*64 + nt*8 + lc2;
            float bx = __ldg(bias + col), by = __ldg(bias + col + 1);
            #pragma unroll
            for (int mt = 0; mt < 2; mt++) {
                int row = m0 + wm*32 + mt*16 + (lane >> 2);
                float2 v0 = make_float2(acc[mt][nt][0] + bx, acc[mt][nt][1] + by);
                float2 v1 = make_float2(acc[mt][nt][2] + bx, acc[mt][nt][3] + by);
                *(float2*)(extC + (size_t)row*NOUT + col)       = v0;
                *(float2*)(extC + (size_t)(row+8)*NOUT + col)   = v1;
            }
        }
    } else {
        // unified K/V epilogue: both hi-only tok-major 64B-row tiles, same swizzle
        const bool isK = (n0 + wn*64) < 256;
        char* arr = isK ? (char*)g_Ks : (char*)g_Vt;
        #pragma unroll
        for (int mt = 0; mt < 2; mt++) {
            int rowb = m0 + wm*32 + mt*16 + (lane >> 2);
            #pragma unroll
            for (int rr = 0; rr < 2; rr++) {
                int r = rowb + rr*8;
                int win = r / 49, tok = r - win*49;
                int key = (tok >> 1) & 3;
                char* base = arr + (size_t)win*(HEADS*4096) + (size_t)tok*64;
                #pragma unroll
                for (int nt = 0; nt < 8; nt++) {
                    int gc = n0 + wn*64 + nt*8 + lc2;
                    float v0 = acc[mt][nt][rr*2]   + __ldg(bias + gc);
                    float v1 = acc[mt][nt][rr*2+1] + __ldg(bias + gc + 1);
                    int c = gc & 255, head = c >> 5, d = c & 31;
                    char* tb = base + head*4096;
                    int chunk = d >> 3, inb = (2*d) & 15;
                    *(uint32_t*)(tb + ((chunk ^ key)*16) + inb)
                        = pkh(__float2half_rn(v0), __float2half_rn(v1));
                }
            }
        }
    }
}

// ---------------- tensor-core attention (fp16, hi-only) ----------------
#define ASMEM (32768 + 32768)   // K 32KB + V 32KB = 64KB
__global__ void __launch_bounds__(256, 3)
attn_k()
{
    extern __shared__ char sm[];
    const int tid = threadIdx.x, b = blockIdx.x;
    const uint32_t sb = smem_u32(sm);

    {   // stage K (group 0), then V (group 1); wait only for K here
        const char* srcK = (const char*)g_Ks + (size_t)b*32768;
        const char* srcV = (const char*)g_Vt + (size_t)b*32768;
        #pragma unroll
        for (int u = 0; u < 8; u++) {
            int i = tid + u*256;
            cp_async16(sb + i*16, srcK + i*16);
        }
        CP_COMMIT();
        #pragma unroll
        for (int u = 0; u < 8; u++) {
            int i = tid + u*256;
            cp_async16(sb + 32768 + i*16, srcV + i*16);
        }
        CP_COMMIT();
        CP_WAIT1();   // K arrived; V still in flight
    }
    __syncthreads();

    const int h = tid >> 5, lane = tid & 31;
    const int img = b >> 6;
    const uint32_t Kt = sb + h*4096;
    const uint32_t Vt = sb + 32768 + h*4096;
    const int lr = lane >> 2, lc2 = 2*(lane & 3);
    const int brow = (lane & 7) + ((lane >> 4) << 3);
    const int bch  = (lane >> 3) & 1;
    const int vrow = lane & 15;
    const int vch  = lane >> 4;

    const uint4*  qf = g_Qf    + ((size_t)(img*HEADS + h)*8)*32 + lane;
    const float4* bf = g_biasF + ((size_t)h*4*7)*32 + lane;

    for (int mt = 0; mt < 4; mt++) {
        uint32_t af[2][4];
        #pragma unroll
        for (int kd = 0; kd < 2; kd++) {
            uint4 v = __ldg(qf + (mt*2 + kd)*32);
            af[kd][0]=v.x; af[kd][1]=v.y; af[kd][2]=v.z; af[kd][3]=v.w;
        }
        float s[8][4];
        #pragma unroll
        for (int nt = 0; nt < 8; nt++)
            #pragma unroll
            for (int j = 0; j < 4; j++) s[nt][j] = 0.f;

        // QK^T: q_hi x k_hi
        #pragma unroll
        for (int np = 0; np < 4; np++) {
            uint32_t kb[2][4];
            int row = np*16 + brow;
            int key = (row >> 1) & 3;
            #pragma unroll
            for (int ch = 0; ch < 2; ch++) {
                int chunk = ch*2 + bch;
                ldmx4(kb[ch], Kt + row*64 + ((chunk ^ key)*16));
            }
            float* s0 = s[2*np]; float* s1 = s[2*np+1];
            mma16816(s0, af[0], kb[0]+0); mma16816(s1, af[0], kb[0]+2);
            mma16816(s0, af[1], kb[1]+0); mma16816(s1, af[1], kb[1]+2);
        }

        // bias (+mask) and softmax over ntiles 0..6
        float mx0 = -1e30f, mx1 = -1e30f;
        #pragma unroll
        for (int nt = 0; nt < 7; nt++) {
            float4 t = __ldg(bf + (mt*7 + nt)*32);
            s[nt][0] += t.x; s[nt][1] += t.y; s[nt][2] += t.z; s[nt][3] += t.w;
            mx0 = fmaxf(mx0, fmaxf(s[nt][0], s[nt][1]));
            mx1 = fmaxf(mx1, fmaxf(s[nt][2], s[nt][3]));
        }
        mx0 = fmaxf(mx0, __shfl_xor_sync(0xFFFFFFFF, mx0, 1));
        mx0 = fmaxf(mx0, __shfl_xor_sync(0xFFFFFFFF, mx0, 2));
        mx1 = fmaxf(mx1, __shfl_xor_sync(0xFFFFFFFF, mx1, 1));
        mx1 = fmaxf(mx1, __shfl_xor_sync(0xFFFFFFFF, mx1, 2));
        float den0 = 0.f, den1 = 0.f;
        #pragma unroll
        for (int nt = 0; nt < 7; nt++) {
            s[nt][0] = __expf(s[nt][0] - mx0); den0 += s[nt][0];
            s[nt][1] = __expf(s[nt][1] - mx0); den0 += s[nt][1];
            s[nt][2] = __expf(s[nt][2] - mx1); den1 += s[nt][2];
            s[nt][3] = __expf(s[nt][3] - mx1); den1 += s[nt][3];
        }
        den0 += __shfl_xor_sync(0xFFFFFFFF, den0, 1);
        den0 += __shfl_xor_sync(0xFFFFFFFF, den0, 2);
        den1 += __shfl_xor_sync(0xFFFFFFFF, den1, 1);
        den1 += __shfl_xor_sync(0xFFFFFFFF, den1, 2);
        float rinv0 = 1.f / den0, rinv1 = 1.f / den1;

        // P -> A fragments (fp16)
        uint32_t ph[4][4];
        #pragma unroll
        for (int ks = 0; ks < 4; ks++) {
            #pragma unroll
            for (int half_ = 0; half_ < 2; half_++) {
                int nt = 2*ks + half_;
                if (nt < 7) {
                    ph[ks][half_*2+0] = pkh(__float2half_rn(s[nt][0]), __float2half_rn(s[nt][1]));
                    ph[ks][half_*2+1] = pkh(__float2half_rn(s[nt][2]), __float2half_rn(s[nt][3]));
                } else {
                    ph[ks][half_*2] = 0; ph[ks][half_*2+1] = 0;
                }
            }
        }

        // before first PV, make sure V staging landed
        if (mt == 0) { CP_WAIT0(); __syncthreads(); }

        // PV: p_hi x v_hi, V via ldmatrix.trans from tok-major tiles
        float o[4][4];
        #pragma unroll
        for (int nt = 0; nt < 4; nt++)
            #pragma unroll
            for (int j = 0; j < 4; j++) o[nt][j] = 0.f;
        #pragma unroll
        for (int ks = 0; ks < 4; ks++) {
            int row = ks*16 + vrow;
            int key = (row >> 1) & 3;
            #pragma unroll
            for (int nh = 0; nh < 2; nh++) {
                uint32_t vh[4];
                int chunk = nh*2 + vch;
                ldmx4t(vh, Vt + row*64 + ((chunk ^ key)*16));
                mma16816(o[2*nh+0], ph[ks], vh+0);
                mma16816(o[2*nh+1], ph[ks], vh+2);
            }
        }

        // store to g_A2 (fp16, [t][256])
        int r0 = mt*16 + lr, r1 = r0 + 8;
        if (r0 < 49) {
            __half* dst = g_A2 + ((size_t)b*NTOK + r0)*KD;
            #pragma unroll
            for (int nt = 0; nt < 4; nt++) {
                int gc = h*HDIM + nt*8 + lc2;
                *(uint32_t*)(dst + gc) = pkh(__float2half_rn(o[nt][0]*rinv0),
                                             __float2half_rn(o[nt][1]*rinv0));
            }
        }
        if (r1 < 49) {
            __half* dst = g_A2 + ((size_t)b*NTOK + r1)*KD;
            #pragma unroll
            for (int nt = 0; nt < 4; nt++) {
                int gc = h*HDIM + nt*8 + lc2;
                *(uint32_t*)(dst + gc) = pkh(__float2half_rn(o[nt][2]*rinv1),
                                             __float2half_rn(o[nt][3]*rinv1));
            }
        }
    }
}

// ---------------- launch ----------------
extern "C" void kernel_launch(void* const* d_in, const int* in_sizes, int n_in,
                              void* d_out, int out_size)
{
    const float* x      = (const float*)d_in[0];
    const float* qg     = (const float*)d_in[1];
    const float* qkv_w  = (const float*)d_in[2];
    const float* qkv_b  = (const float*)d_in[3];
    const float* proj_w = (const float*)d_in[4];
    const float* proj_b = (const float*)d_in[5];
    const float* rbt    = (const float*)d_in[6];
    float* out = (float*)d_out;
    (void)in_sizes; (void)n_in; (void)out_size;

    cudaFuncSetAttribute(gemm_k<512>, cudaFuncAttributeMaxDynamicSharedMemorySize, GSMEM);
    cudaFuncSetAttribute(gemm_k<256>, cudaFuncAttributeMaxDynamicSharedMemorySize, GSMEM);
    cudaFuncSetAttribute(attn_k,      cudaFuncAttributeMaxDynamicSharedMemorySize, ASMEM);

    prep_all<<<512, 256>>>(qkv_w, proj_w, rbt, qg);
    conv_x<<<4096, 256>>>(x);
    {
        dim3 g1(4, TOKS/128);
        gemm_k<512><<<g1, 256, GSMEM>>>(qkv_b, nullptr);
    }
    attn_k<<<BWIN, 256, ASMEM>>>();
    {
        dim3 g2(2, TOKS/128);
        gemm_k<256><<<g2, 256, GSMEM>>>(proj_b, out);
    }
}

// round 11
// speedup vs baseline: 3.7480x; 1.0977x over previous
#include <cuda_runtime.h>
#include <cuda_fp16.h>
#include <cstdint>
#include <math.h>

#define NTOK   49
#define CDIM   256
#define HEADS  8
#define HDIM   32
#define BWIN   4096
#define TOKS   (BWIN*NTOK)          // 200704 = 1568 * 128
#define KD     256                  // plain fp16
#define NITER  4                    // K/64
#define SCALE  0.17677669529663688f
#define LOG2E  1.4426950408889634f

// ---------------- scratch (device globals; no allocs) ----------------
__device__ __half g_A1[(size_t)TOKS*KD];   // fp16(x)   [t][256]
__device__ __half g_A2[(size_t)TOKS*KD];   // attn-out  [t][256]
__device__ __half g_B1[512*KD];            // fp16(qkv_w)
__device__ __half g_B2[256*KD];            // fp16(proj_w)
// K and V tiles: [win][head] 64 tok-rows x 64B (32 fp16), swizzle key (tok>>1)&3. pads stay 0.
__device__ unsigned char g_Ks[(size_t)BWIN*HEADS*4096];
__device__ unsigned char g_Vt[(size_t)BWIN*HEADS*4096];
// Q fragments: [img][head][mtile 4][kind 2][lane 32] uint4 (pre-scaled by SCALE*LOG2E)
__device__ uint4  g_Qf[64*HEADS*4*2*32];
// bias in C-fragment layout, x LOG2E, mask folded: [head][mtile 4][ntile 7][lane 32] float4
__device__ float4 g_biasF[HEADS*4*7*32];

// ---------------- helpers ----------------
__device__ __forceinline__ uint32_t smem_u32(const void* p){
    uint32_t a;
    asm("{ .reg .u64 t; cvta.to.shared.u64 t, %1; cvt.u32.u64 %0, t; }" : "=r"(a) : "l"(p));
    return a;
}
__device__ __forceinline__ void cp_async16(uint32_t dst, const void* src){
    asm volatile("cp.async.cg.shared.global [%0], [%1], 16;" :: "r"(dst), "l"(src));
}
#define CP_COMMIT() asm volatile("cp.async.commit_group;")
#define CP_WAIT1()  asm volatile("cp.async.wait_group 1;")
#define CP_WAIT0()  asm volatile("cp.async.wait_group 0;")

__device__ __forceinline__ void ldmx4(uint32_t* r, uint32_t addr){
    asm volatile("ldmatrix.sync.aligned.m8n8.x4.shared.b16 {%0,%1,%2,%3}, [%4];"
        : "=r"(r[0]), "=r"(r[1]), "=r"(r[2]), "=r"(r[3]) : "r"(addr));
}
__device__ __forceinline__ void ldmx4t(uint32_t* r, uint32_t addr){
    asm volatile("ldmatrix.sync.aligned.m8n8.x4.trans.shared.b16 {%0,%1,%2,%3}, [%4];"
        : "=r"(r[0]), "=r"(r[1]), "=r"(r[2]), "=r"(r[3]) : "r"(addr));
}
__device__ __forceinline__ void mma16816(float* c, const uint32_t* a, const uint32_t* b){
    asm volatile("mma.sync.aligned.m16n8k16.row.col.f32.f16.f16.f32 "
        "{%0,%1,%2,%3}, {%4,%5,%6,%7}, {%8,%9}, {%0,%1,%2,%3};"
        : "+f"(c[0]), "+f"(c[1]), "+f"(c[2]), "+f"(c[3])
        : "r"(a[0]), "r"(a[1]), "r"(a[2]), "r"(a[3]), "r"(b[0]), "r"(b[1]));
}
__device__ __forceinline__ uint32_t pkh(__half a, __half b){
    return (uint32_t)__half_as_ushort(a) | ((uint32_t)__half_as_ushort(b) << 16);
}
__device__ __forceinline__ uint32_t pk2f(float a, float b){
    __half2 h = __floats2half2_rn(a, b);
    return *reinterpret_cast<uint32_t*>(&h);
}
__device__ __forceinline__ int rpi(int r, int c){
    int ai = r/7, aj = r%7, bi = c/7, bj = c%7;
    return (ai - bi + 6)*13 + (aj - bj + 6);
}

// ------- prep (weights, bias, Q frags) + conv_x merged, grid 4096x256 -------
__global__ void prep_conv(const float* __restrict__ qkv_w,
                          const float* __restrict__ proj_w,
                          const float* __restrict__ rbt,
                          const float* __restrict__ qg,
                          const float* __restrict__ x)
{
    int idx = blockIdx.x * 256 + threadIdx.x;
    if (idx < 512*256) g_B1[idx] = __float2half_rn(qkv_w[idx]);
    if (idx < 256*256) g_B2[idx] = __float2half_rn(proj_w[idx]);
    if (idx < HEADS*4*7*32) {
        int lane = idx & 31;
        int nt = (idx >> 5) % 7;
        int mt = (idx >> 5) / 7 % 4;
        int h  = idx / (32*7*4);
        int r0 = mt*16 + (lane>>2), r1 = r0 + 8;
        int c0 = nt*8 + 2*(lane&3), c1 = c0 + 1;
        float4 v;
        v.x = (r0 < 49 && c0 < 49) ? rbt[rpi(r0,c0)*HEADS + h]*LOG2E : -1e30f;
        v.y = (r0 < 49 && c1 < 49) ? rbt[rpi(r0,c1)*HEADS + h]*LOG2E : -1e30f;
        v.z = (r1 < 49 && c0 < 49) ? rbt[rpi(r1,c0)*HEADS + h]*LOG2E : -1e30f;
        v.w = (r1 < 49 && c1 < 49) ? rbt[rpi(r1,c1)*HEADS + h]*LOG2E : -1e30f;
        g_biasF[idx] = v;
    }
    if (idx < 64*HEADS*4*2*32) {   // Q fragments, pre-scaled by SCALE*LOG2E
        int lane = idx & 31;
        int kind = (idx >> 5) & 1;
        int mt   = (idx >> 6) & 3;
        int h    = (idx >> 8) & 7;
        int img  = idx >> 11;
        int r = mt*16 + (lane>>2);
        int c2 = 2*(lane&3);
        int db = kind * 16;
        const float qs = SCALE * LOG2E;
        auto qget = [&](int rr, int d) -> float {
            if (rr >= 49) return 0.f;
            return qg[(((size_t)img*HEADS + h)*NTOK + rr)*HDIM + d] * qs;
        };
        uint4 o;
        o.x = pk2f(qget(r,   db+c2),   qget(r,   db+c2+1));
        o.y = pk2f(qget(r+8, db+c2),   qget(r+8, db+c2+1));
        o.z = pk2f(qget(r,   db+c2+8), qget(r,   db+c2+9));
        o.w = pk2f(qget(r+8, db+c2+8), qget(r+8, db+c2+9));
        g_Qf[idx] = o;
    }
    // conv_x: grid-stride over TOKS*64 float4s
    {
        const float4* x4 = (const float4*)x;
        int stride = gridDim.x * 256;
        for (int i = idx; i < TOKS*64; i += stride) {
            float4 v = __ldg(x4 + i);
            *(uint2*)(g_A1 + (size_t)i*4) = make_uint2(pk2f(v.x, v.y), pk2f(v.z, v.w));
        }
    }
}

// ---------------- mma.sync fp16 GEMM: C[128,128] per CTA, K=256 ------------
#define GSTAGE 16384
#define GSMEM  (3*2*GSTAGE)    // 96 KB

template<int NOUT>
__global__ void __launch_bounds__(256, 2)
gemm_k(const float* __restrict__ bias, float* __restrict__ extC)
{
    extern __shared__ char sm[];
    const __half* Ag = (NOUT == 512) ? g_A1 : g_A2;
    const __half* Bg = (NOUT == 512) ? g_B1 : g_B2;

    const int tid = threadIdx.x;
    const int n0 = blockIdx.x * 128;
    const int m0 = blockIdx.y * 128;
    const uint32_t sb = smem_u32(sm);

    auto load_stage = [&](int i, int s){
        const char* Abase = (const char*)Ag + ((size_t)m0*KD + (size_t)i*64)*2;
        const char* Bbase = (const char*)Bg + ((size_t)n0*KD + (size_t)i*64)*2;
        uint32_t sa  = sb + s*2*GSTAGE;
        uint32_t sbB = sa + GSTAGE;
        #pragma unroll
        for (int u = 0; u < 4; u++) {
            int idx = tid + u*256;
            int r = idx >> 3, c16 = idx & 7;
            uint32_t dst = (uint32_t)(r*128 + ((c16 ^ (r & 7))*16));
            cp_async16(sa  + dst, Abase + (size_t)r*(KD*2) + c16*16);
            cp_async16(sbB + dst, Bbase + (size_t)r*(KD*2) + c16*16);
        }
        CP_COMMIT();
    };

    const int w = tid >> 5, lane = tid & 31;
    const int wm = w >> 1, wn = w & 1;
    const int aRow = wm*32 + (lane & 15);
    const int aC16 = (lane >> 4);
    const int bRow = wn*64 + (lane & 7) + ((lane >> 4) << 3);
    const int bC16 = (lane >> 3) & 1;
    const int lc2 = 2*(lane & 3);

    float acc[2][8][4];
    #pragma unroll
    for (int mt = 0; mt < 2; mt++)
        #pragma unroll
        for (int nt = 0; nt < 8; nt++)
            #pragma unroll
            for (int q = 0; q < 4; q++) acc[mt][nt][q] = 0.f;

    load_stage(0, 0);
    load_stage(1, 1);
    int s = 0;
    for (int i = 0; i < NITER; i++) {
        if (i < NITER-1) { CP_WAIT1(); } else { CP_WAIT0(); }
        __syncthreads();
        if (i + 2 < NITER) {
            int s2 = s + 2; if (s2 >= 3) s2 -= 3;
            load_stage(i + 2, s2);
        }
        const uint32_t sa  = sb + s*2*GSTAGE;
        const uint32_t sbB = sa + GSTAGE;
        uint32_t af[4][2][4];
        #pragma unroll
        for (int kk = 0; kk < 4; kk++)
            #pragma unroll
            for (int mt = 0; mt < 2; mt++) {
                int r = aRow + mt*16, c = kk*2 + aC16;
                ldmx4(af[kk][mt], sa + r*128 + ((c ^ (r & 7))*16));
            }
        #pragma unroll
        for (int kk = 0; kk < 4; kk++) {
            #pragma unroll
            for (int np = 0; np < 4; np++) {
                uint32_t bf[4];
                int r = bRow + np*16, c = kk*2 + bC16;
                ldmx4(bf, sbB + r*128 + ((c ^ (r & 7))*16));
                #pragma unroll
                for (int mt = 0; mt < 2; mt++) {
                    mma16816(acc[mt][np*2+0], af[kk][mt], bf+0);
                    mma16816(acc[mt][np*2+1], af[kk][mt], bf+2);
                }
            }
        }
        if (++s >= 3) s -= 3;
    }

    if (NOUT == 256) {
        #pragma unroll
        for (int nt = 0; nt < 8; nt++) {
            int col = n0 + wn*64 + nt*8 + lc2;
            float bx = __ldg(bias + col), by = __ldg(bias + col + 1);
            #pragma unroll
            for (int mt = 0; mt < 2; mt++) {
                int row = m0 + wm*32 + mt*16 + (lane >> 2);
                float2 v0 = make_float2(acc[mt][nt][0] + bx, acc[mt][nt][1] + by);
                float2 v1 = make_float2(acc[mt][nt][2] + bx, acc[mt][nt][3] + by);
                *(float2*)(extC + (size_t)row*NOUT + col)       = v0;
                *(float2*)(extC + (size_t)(row+8)*NOUT + col)   = v1;
            }
        }
    } else {
        // unified K/V epilogue: both hi-only tok-major 64B-row tiles, same swizzle
        const bool isK = (n0 + wn*64) < 256;
        char* arr = isK ? (char*)g_Ks : (char*)g_Vt;
        #pragma unroll
        for (int mt = 0; mt < 2; mt++) {
            int rowb = m0 + wm*32 + mt*16 + (lane >> 2);
            #pragma unroll
            for (int rr = 0; rr < 2; rr++) {
                int r = rowb + rr*8;
                int win = r / 49, tok = r - win*49;
                int key = (tok >> 1) & 3;
                char* base = arr + (size_t)win*(HEADS*4096) + (size_t)tok*64;
                #pragma unroll
                for (int nt = 0; nt < 8; nt++) {
                    int gc = n0 + wn*64 + nt*8 + lc2;
                    float v0 = acc[mt][nt][rr*2]   + __ldg(bias + gc);
                    float v1 = acc[mt][nt][rr*2+1] + __ldg(bias + gc + 1);
                    int c = gc & 255, head = c >> 5, d = c & 31;
                    char* tb = base + head*4096;
                    int chunk = d >> 3, inb = (2*d) & 15;
                    *(uint32_t*)(tb + ((chunk ^ key)*16) + inb) = pk2f(v0, v1);
                }
            }
        }
    }
}

// ---------------- tensor-core attention (fp16, exp2 softmax, no max-pass) ---
#define ASMEM (32768 + 32768)   // K 32KB + V 32KB = 64KB
__global__ void __launch_bounds__(256, 3)
attn_k()
{
    extern __shared__ char sm[];
    const int tid = threadIdx.x, b = blockIdx.x;
    const uint32_t sb = smem_u32(sm);

    {   // stage K (group 0), then V (group 1); wait only for K here
        const char* srcK = (const char*)g_Ks + (size_t)b*32768;
        const char* srcV = (const char*)g_Vt + (size_t)b*32768;
        #pragma unroll
        for (int u = 0; u < 8; u++) {
            int i = tid + u*256;
            cp_async16(sb + i*16, srcK + i*16);
        }
        CP_COMMIT();
        #pragma unroll
        for (int u = 0; u < 8; u++) {
            int i = tid + u*256;
            cp_async16(sb + 32768 + i*16, srcV + i*16);
        }
        CP_COMMIT();
        CP_WAIT1();   // K arrived; V still in flight
    }
    __syncthreads();

    const int h = tid >> 5, lane = tid & 31;
    const int img = b >> 6;
    const uint32_t Kt = sb + h*4096;
    const uint32_t Vt = sb + 32768 + h*4096;
    const int lr = lane >> 2, lc2 = 2*(lane & 3);
    const int brow = (lane & 7) + ((lane >> 4) << 3);
    const int bch  = (lane >> 3) & 1;
    const int vrow = lane & 15;
    const int vch  = lane >> 4;

    const uint4*  qf = g_Qf    + ((size_t)(img*HEADS + h)*8)*32 + lane;
    const float4* bf = g_biasF + ((size_t)h*4*7)*32 + lane;

    for (int mt = 0; mt < 4; mt++) {
        uint32_t af[2][4];
        #pragma unroll
        for (int kd = 0; kd < 2; kd++) {
            uint4 v = __ldg(qf + (mt*2 + kd)*32);
            af[kd][0]=v.x; af[kd][1]=v.y; af[kd][2]=v.z; af[kd][3]=v.w;
        }
        float s[8][4];
        #pragma unroll
        for (int nt = 0; nt < 8; nt++)
            #pragma unroll
            for (int j = 0; j < 4; j++) s[nt][j] = 0.f;

        // QK^T in log2 domain (Q pre-scaled by SCALE*log2e)
        #pragma unroll
        for (int np = 0; np < 4; np++) {
            uint32_t kb[2][4];
            int row = np*16 + brow;
            int key = (row >> 1) & 3;
            #pragma unroll
            for (int ch = 0; ch < 2; ch++) {
                int chunk = ch*2 + bch;
                ldmx4(kb[ch], Kt + row*64 + ((chunk ^ key)*16));
            }
            float* s0 = s[2*np]; float* s1 = s[2*np+1];
            mma16816(s0, af[0], kb[0]+0); mma16816(s1, af[0], kb[0]+2);
            mma16816(s0, af[1], kb[1]+0); mma16816(s1, af[1], kb[1]+2);
        }

        // softmax (no max-pass: scores bounded, see analysis); p = exp2(s + bias2)
        float den0 = 0.f, den1 = 0.f;
        #pragma unroll
        for (int nt = 0; nt < 7; nt++) {
            float4 t = __ldg(bf + (mt*7 + nt)*32);
            s[nt][0] = exp2f(s[nt][0] + t.x); den0 += s[nt][0];
            s[nt][1] = exp2f(s[nt][1] + t.y); den0 += s[nt][1];
            s[nt][2] = exp2f(s[nt][2] + t.z); den1 += s[nt][2];
            s[nt][3] = exp2f(s[nt][3] + t.w); den1 += s[nt][3];
        }
        den0 += __shfl_xor_sync(0xFFFFFFFF, den0, 1);
        den0 += __shfl_xor_sync(0xFFFFFFFF, den0, 2);
        den1 += __shfl_xor_sync(0xFFFFFFFF, den1, 1);
        den1 += __shfl_xor_sync(0xFFFFFFFF, den1, 2);
        float rinv0 = 1.f / den0, rinv1 = 1.f / den1;

        // P -> A fragments (fp16, packed cvt)
        uint32_t ph[4][4];
        #pragma unroll
        for (int ks = 0; ks < 4; ks++) {
            #pragma unroll
            for (int half_ = 0; half_ < 2; half_++) {
                int nt = 2*ks + half_;
                if (nt < 7) {
                    ph[ks][half_*2+0] = pk2f(s[nt][0], s[nt][1]);
                    ph[ks][half_*2+1] = pk2f(s[nt][2], s[nt][3]);
                } else {
                    ph[ks][half_*2] = 0; ph[ks][half_*2+1] = 0;
                }
            }
        }

        // before first PV, make sure V staging landed
        if (mt == 0) { CP_WAIT0(); __syncthreads(); }

        // PV: p x v, V via ldmatrix.trans from tok-major tiles
        float o[4][4];
        #pragma unroll
        for (int nt = 0; nt < 4; nt++)
            #pragma unroll
            for (int j = 0; j < 4; j++) o[nt][j] = 0.f;
        #pragma unroll
        for (int ks = 0; ks < 4; ks++) {
            int row = ks*16 + vrow;
            int key = (row >> 1) & 3;
            #pragma unroll
            for (int nh = 0; nh < 2; nh++) {
                uint32_t vh[4];
                int chunk = nh*2 + vch;
                ldmx4t(vh, Vt + row*64 + ((chunk ^ key)*16));
                mma16816(o[2*nh+0], ph[ks], vh+0);
                mma16816(o[2*nh+1], ph[ks], vh+2);
            }
        }

        // store to g_A2 (fp16, [t][256]), packed cvt
        int r0 = mt*16 + lr, r1 = r0 + 8;
        if (r0 < 49) {
            __half* dst = g_A2 + ((size_t)b*NTOK + r0)*KD;
            #pragma unroll
            for (int nt = 0; nt < 4; nt++) {
                int gc = h*HDIM + nt*8 + lc2;
                *(uint32_t*)(dst + gc) = pk2f(o[nt][0]*rinv0, o[nt][1]*rinv0);
            }
        }
        if (r1 < 49) {
            __half* dst = g_A2 + ((size_t)b*NTOK + r1)*KD;
            #pragma unroll
            for (int nt = 0; nt < 4; nt++) {
                int gc = h*HDIM + nt*8 + lc2;
                *(uint32_t*)(dst + gc) = pk2f(o[nt][2]*rinv1, o[nt][3]*rinv1);
            }
        }
    }
}

// ---------------- launch ----------------
extern "C" void kernel_launch(void* const* d_in, const int* in_sizes, int n_in,
                              void* d_out, int out_size)
{
    const float* x      = (const float*)d_in[0];
    const float* qg     = (const float*)d_in[1];
    const float* qkv_w  = (const float*)d_in[2];
    const float* qkv_b  = (const float*)d_in[3];
    const float* proj_w = (const float*)d_in[4];
    const float* proj_b = (const float*)d_in[5];
    const float* rbt    = (const float*)d_in[6];
    float* out = (float*)d_out;
    (void)in_sizes; (void)n_in; (void)out_size;

    cudaFuncSetAttribute(gemm_k<512>, cudaFuncAttributeMaxDynamicSharedMemorySize, GSMEM);
    cudaFuncSetAttribute(gemm_k<256>, cudaFuncAttributeMaxDynamicSharedMemorySize, GSMEM);
    cudaFuncSetAttribute(attn_k,      cudaFuncAttributeMaxDynamicSharedMemorySize, ASMEM);

    prep_conv<<<4096, 256>>>(qkv_w, proj_w, rbt, qg, x);
    {
        dim3 g1(4, TOKS/128);
        gemm_k<512><<<g1, 256, GSMEM>>>(qkv_b, nullptr);
    }
    attn_k<<<BWIN, 256, ASMEM>>>();
    {
        dim3 g2(2, TOKS/128);
        gemm_k<256><<<g2, 256, GSMEM>>>(proj_b, out);
    }
}